// round 5
// baseline (speedup 1.0000x reference)
#include <cuda_runtime.h>
#include <math.h>
#include <stdint.h>

// Problem dimensions (fixed by the reference)
#define B_SZ 16
#define S_SZ 512
#define W_SZ 5
#define D_SZ 200
#define H_SZ 768
#define M1 (B_SZ * S_SZ * W_SZ)   // 40960
#define MQ (B_SZ * S_SZ)          // 8192
#define NMASK (MQ * W_SZ)         // 40960

// Scratch (alloc-free rule: __device__ globals)
__device__ float g_tmp[M1 * H_SZ];     // tanh(WE @ W1 + b1), tf32-rounded
__device__ float g_we [M1 * H_SZ];     // word_transform output (fp32)
__device__ float g_q  [MQ * H_SZ];     // layer_output @ attn_W (fp32)
__device__ float g_maskf[NMASK];
__device__ int   g_mask_is32;
// tf32-pre-rounded AND transposed weights: [N][K] row-major
__device__ float g_W1T[H_SZ * D_SZ];
__device__ float g_W2T[H_SZ * H_SZ];
__device__ float g_aWT[H_SZ * H_SZ];

__device__ __forceinline__ uint32_t f2tf32(float f)
{
    uint32_t u;
    asm("cvt.rna.tf32.f32 %0, %1;\n" : "=r"(u) : "f"(f));
    return u;
}

// ---------------------------------------------------------------------------
// Transpose + round weights: in[K][N] -> out[N][K], tf32-rounded bits
// ---------------------------------------------------------------------------
__global__ void transpose_round_kernel(const float* __restrict__ in,
                                       float* __restrict__ out,
                                       int K, int N)
{
    __shared__ float tile[32][33];
    int x = blockIdx.x * 32 + threadIdx.x;   // col in input (n)
    int y0 = blockIdx.y * 32;                // row block in input (k)
    #pragma unroll
    for (int j = 0; j < 32; j += 8) {
        int y = y0 + threadIdx.y + j;
        if (y < K && x < N)
            tile[threadIdx.y + j][threadIdx.x] = in[(size_t)y * N + x];
    }
    __syncthreads();
    int ox = y0 + threadIdx.x;               // col in output (k)
    int oy0 = blockIdx.x * 32;               // row block in output (n)
    #pragma unroll
    for (int j = 0; j < 32; j += 8) {
        int oy = oy0 + threadIdx.y + j;
        if (oy < N && ox < K)
            out[(size_t)oy * K + ox] =
                __uint_as_float(f2tf32(tile[threadIdx.x][threadIdx.y + j]));
    }
}

// ---------------------------------------------------------------------------
// Mask dtype detection + normalization (proven since R2)
// ---------------------------------------------------------------------------
__global__ void detect_mask_kernel(const long long* __restrict__ m64)
{
    int i = blockIdx.x * blockDim.x + threadIdx.x;
    if (i < NMASK / 2) {
        unsigned long long v = (unsigned long long)m64[i];
        if (v > 1ULL) atomicOr(&g_mask_is32, 1);
    }
}
__global__ void normalize_mask_kernel(const void* __restrict__ mraw)
{
    int i = blockIdx.x * blockDim.x + threadIdx.x;
    if (i >= NMASK) return;
    float v;
    if (g_mask_is32) v = (float)((const int*)mraw)[i];
    else             v = (float)((const long long*)mraw)[i];
    g_maskf[i] = v;
}

// ---------------------------------------------------------------------------
// TF32 tensor-core GEMM with ldmatrix fragment loads.
// C[M,N] = op(A[M,K] @ Bt[N,K]^T + bias)
// BM=128, BN=128, BK=32, 128 threads = 4 warps (2x2), warp tile 64x64.
// A smem [m][k] stride 36; B smem [n][k] stride 36 (Bt global is [N][K]).
// Both fragment types load via ldmatrix.m8n8.x4.b16 (8x4-tf32 tiles).
// ---------------------------------------------------------------------------
#define TS_STRIDE 36
#define TILE_ELEMS (128 * TS_STRIDE)
#define SMEM_BYTES (4 * TILE_ELEMS * 4)   // A0,A1,B0,B1 = 73728 B

__device__ __forceinline__ void cp_async16(uint32_t dst, const void* src, int ssize)
{
    asm volatile("cp.async.cg.shared.global [%0], [%1], 16, %2;\n"
                 :: "r"(dst), "l"(src), "r"(ssize));
}
__device__ __forceinline__ void cp_commit() { asm volatile("cp.async.commit_group;\n"); }
__device__ __forceinline__ void cp_wait0()  { asm volatile("cp.async.wait_group 0;\n"); }

__device__ __forceinline__ void ldsm_x4(uint32_t& r0, uint32_t& r1,
                                        uint32_t& r2, uint32_t& r3, uint32_t addr)
{
    asm volatile("ldmatrix.sync.aligned.m8n8.x4.shared.b16 {%0,%1,%2,%3}, [%4];\n"
                 : "=r"(r0), "=r"(r1), "=r"(r2), "=r"(r3) : "r"(addr));
}

template <bool TANH, bool BIAS, bool CVT_A, bool ROUND_OUT>
__global__ __launch_bounds__(128, 2)
void tf32_gemm(const float* __restrict__ A,
               const float* __restrict__ Bt,   // [N][K] pre-rounded tf32
               const float* __restrict__ bias,
               float* __restrict__ C,
               int M, int N, int K)
{
    extern __shared__ float smem[];
    float* As[2] = { smem,                  smem + TILE_ELEMS };
    float* Bs[2] = { smem + 2 * TILE_ELEMS, smem + 3 * TILE_ELEMS };

    const int tid  = threadIdx.x;       // 0..127
    const int lane = tid & 31;
    const int wid  = tid >> 5;          // 0..3
    const int wm   = (wid & 1) * 64;
    const int wn   = (wid >> 1) * 64;
    const int g    = lane >> 2;
    const int tg   = lane & 3;
    const int m0   = blockIdx.y * 128;
    const int n0   = blockIdx.x * 128;

    // ldmatrix per-lane tile-row / k-offset
    const int lrow = (lane & 7) + ((lane >> 3) & 1) * 8;  // row within 16-row group
    const int lko  = (lane >> 4) * 4;                      // k offset: 0 or 4

    // cp.async coords: tile 128 rows x 32 k -> 1024 float4, 8/thread
    int rrow[8];
    #pragma unroll
    for (int i = 0; i < 8; i++) rrow[i] = (tid + i * 128) >> 3;
    const int ac = (tid & 7) * 4;

    uint32_t as_base[2], bs_base[2];
    as_base[0] = (uint32_t)__cvta_generic_to_shared(As[0]);
    as_base[1] = (uint32_t)__cvta_generic_to_shared(As[1]);
    bs_base[0] = (uint32_t)__cvta_generic_to_shared(Bs[0]);
    bs_base[1] = (uint32_t)__cvta_generic_to_shared(Bs[1]);

    float acc[4][8][4];
    #pragma unroll
    for (int mi = 0; mi < 4; mi++)
        #pragma unroll
        for (int ni = 0; ni < 8; ni++)
            #pragma unroll
            for (int r = 0; r < 4; r++)
                acc[mi][ni][r] = 0.f;

    const int tiles = (K + 31) / 32;

    auto load_tile = [&](int buf, int k0) {
        int gk = k0 + ac;
        int ok = (gk < K) ? 16 : 0;
        int gks = ok ? gk : 0;
        #pragma unroll
        for (int i = 0; i < 8; i++) {
            cp_async16(as_base[buf] + (rrow[i] * TS_STRIDE + ac) * 4,
                       A + (size_t)(m0 + rrow[i]) * K + gks, ok);
        }
        #pragma unroll
        for (int i = 0; i < 8; i++) {
            cp_async16(bs_base[buf] + (rrow[i] * TS_STRIDE + ac) * 4,
                       Bt + (size_t)(n0 + rrow[i]) * K + gks, ok);
        }
        cp_commit();
    };

    load_tile(0, 0);

    int buf = 0;
    for (int t = 0; t < tiles; t++) {
        cp_wait0();
        __syncthreads();
        if (t + 1 < tiles)
            load_tile(buf ^ 1, (t + 1) * 32);

        const uint32_t a_ld_base = as_base[buf] + ((wm + lrow) * TS_STRIDE + lko) * 4;
        const uint32_t b_ld_base = bs_base[buf] + ((wn + lrow) * TS_STRIDE + lko) * 4;

        #pragma unroll
        for (int s = 0; s < 4; s++) {
            const int kb4 = s * 8 * 4;   // byte offset of k-block
            uint32_t af[4][4];
            #pragma unroll
            for (int mi = 0; mi < 4; mi++) {
                ldsm_x4(af[mi][0], af[mi][1], af[mi][2], af[mi][3],
                        a_ld_base + mi * 16 * TS_STRIDE * 4 + kb4);
                if (CVT_A) {
                    af[mi][0] = f2tf32(__uint_as_float(af[mi][0]));
                    af[mi][1] = f2tf32(__uint_as_float(af[mi][1]));
                    af[mi][2] = f2tf32(__uint_as_float(af[mi][2]));
                    af[mi][3] = f2tf32(__uint_as_float(af[mi][3]));
                }
            }
            uint32_t bf[8][2];
            #pragma unroll
            for (int ni2 = 0; ni2 < 4; ni2++) {
                uint32_t t0, t1, t2, t3;
                ldsm_x4(t0, t1, t2, t3,
                        b_ld_base + ni2 * 16 * TS_STRIDE * 4 + kb4);
                bf[2 * ni2][0]     = t0;
                bf[2 * ni2 + 1][0] = t1;
                bf[2 * ni2][1]     = t2;
                bf[2 * ni2 + 1][1] = t3;
            }
            #pragma unroll
            for (int mi = 0; mi < 4; mi++)
                #pragma unroll
                for (int ni = 0; ni < 8; ni++) {
                    asm volatile(
                        "mma.sync.aligned.m16n8k8.row.col.f32.tf32.tf32.f32 "
                        "{%0,%1,%2,%3}, {%4,%5,%6,%7}, {%8,%9}, {%0,%1,%2,%3};\n"
                        : "+f"(acc[mi][ni][0]), "+f"(acc[mi][ni][1]),
                          "+f"(acc[mi][ni][2]), "+f"(acc[mi][ni][3])
                        : "r"(af[mi][0]), "r"(af[mi][1]), "r"(af[mi][2]), "r"(af[mi][3]),
                          "r"(bf[ni][0]), "r"(bf[ni][1]));
                }
        }
        buf ^= 1;
    }

    // epilogue
    #pragma unroll
    for (int ni = 0; ni < 8; ni++) {
        const int col = n0 + wn + ni * 8 + tg * 2;
        float b0 = 0.f, b1 = 0.f;
        if (BIAS) { b0 = bias[col]; b1 = bias[col + 1]; }
        #pragma unroll
        for (int mi = 0; mi < 4; mi++) {
            const int row = m0 + wm + mi * 16 + g;
            float r0 = acc[mi][ni][0] + b0;
            float r1 = acc[mi][ni][1] + b1;
            float r2 = acc[mi][ni][2] + b0;
            float r3 = acc[mi][ni][3] + b1;
            if (TANH) { r0 = tanhf(r0); r1 = tanhf(r1); r2 = tanhf(r2); r3 = tanhf(r3); }
            if (ROUND_OUT) {
                r0 = __uint_as_float(f2tf32(r0));
                r1 = __uint_as_float(f2tf32(r1));
                r2 = __uint_as_float(f2tf32(r2));
                r3 = __uint_as_float(f2tf32(r3));
            }
            *reinterpret_cast<float2*>(&C[(size_t)row * N + col])       = make_float2(r0, r1);
            *reinterpret_cast<float2*>(&C[(size_t)(row + 8) * N + col]) = make_float2(r2, r3);
        }
    }
}

// ---------------------------------------------------------------------------
// Fused epilogue (unchanged, proven since R2)
// ---------------------------------------------------------------------------
__global__ __launch_bounds__(256)
void epilogue_kernel(const float* __restrict__ lo,
                     const float* __restrict__ gamma,
                     const float* __restrict__ beta,
                     float* __restrict__ out)
{
    const int bs  = blockIdx.x;
    const int tid = threadIdx.x;

    __shared__ float red[5][256];
    __shared__ float s_alpha[5];

    const float* qrow  = g_q  + (size_t)bs * H_SZ;
    const float* werow = g_we + (size_t)bs * W_SZ * H_SZ;
    const float* lorow = lo   + (size_t)bs * H_SZ;

    float qv[3], lov[3], wev[5][3];
    #pragma unroll
    for (int e = 0; e < 3; e++) {
        int h = tid + e * 256;
        qv[e]  = qrow[h];
        lov[e] = lorow[h];
        #pragma unroll
        for (int w = 0; w < W_SZ; w++)
            wev[w][e] = werow[w * H_SZ + h];
    }

    #pragma unroll
    for (int w = 0; w < W_SZ; w++) {
        float d = 0.f;
        #pragma unroll
        for (int e = 0; e < 3; e++)
            d = fmaf(qv[e], wev[w][e], d);
        red[w][tid] = d;
    }
    __syncthreads();
    for (int s = 128; s > 0; s >>= 1) {
        if (tid < s) {
            #pragma unroll
            for (int w = 0; w < W_SZ; w++)
                red[w][tid] += red[w][tid + s];
        }
        __syncthreads();
    }

    if (tid == 0) {
        float sc[5];
        float mx = -1e30f;
        #pragma unroll
        for (int w = 0; w < W_SZ; w++) {
            float mk = g_maskf[(size_t)bs * W_SZ + w];
            sc[w] = red[w][0] + (1.f - mk) * (-10000.f);
            mx = fmaxf(mx, sc[w]);
        }
        float sum = 0.f;
        #pragma unroll
        for (int w = 0; w < W_SZ; w++) {
            sc[w] = expf(sc[w] - mx);
            sum += sc[w];
        }
        float inv = 1.f / sum;
        #pragma unroll
        for (int w = 0; w < W_SZ; w++)
            s_alpha[w] = sc[w] * inv;
    }
    __syncthreads();

    float alpha[5];
    #pragma unroll
    for (int w = 0; w < W_SZ; w++) alpha[w] = s_alpha[w];

    float hv[3];
    float psum = 0.f, psq = 0.f;
    #pragma unroll
    for (int e = 0; e < 3; e++) {
        float agg = 0.f;
        #pragma unroll
        for (int w = 0; w < W_SZ; w++)
            agg = fmaf(alpha[w], wev[w][e], agg);
        hv[e] = lov[e] + agg;
        psum += hv[e];
        psq  = fmaf(hv[e], hv[e], psq);
    }
    __syncthreads();
    red[0][tid] = psum;
    red[1][tid] = psq;
    __syncthreads();
    for (int s = 128; s > 0; s >>= 1) {
        if (tid < s) {
            red[0][tid] += red[0][tid + s];
            red[1][tid] += red[1][tid + s];
        }
        __syncthreads();
    }

    const float inv_h = 1.f / (float)H_SZ;
    float mu   = red[0][0] * inv_h;
    float var  = red[1][0] * inv_h - mu * mu;
    float rstd = rsqrtf(var + 1e-12f);

    #pragma unroll
    for (int e = 0; e < 3; e++) {
        int h = tid + e * 256;
        out[(size_t)bs * H_SZ + h] = (hv[e] - mu) * rstd * gamma[h] + beta[h];
    }
}

// ---------------------------------------------------------------------------
// Launch
// ---------------------------------------------------------------------------
extern "C" void kernel_launch(void* const* d_in, const int* in_sizes, int n_in,
                              void* d_out, int out_size)
{
    const float* lo     = (const float*)d_in[0];
    const float* we_in  = (const float*)d_in[1];
    const void*  mask   = d_in[2];
    const float* W1     = (const float*)d_in[3];
    const float* b1     = (const float*)d_in[4];
    const float* W2     = (const float*)d_in[5];
    const float* b2     = (const float*)d_in[6];
    const float* attn_W = (const float*)d_in[7];
    const float* gamma  = (const float*)d_in[8];
    const float* beta   = (const float*)d_in[9];
    float*       out    = (float*)d_out;

    float *tmp_p, *we_p, *q_p, *w1t_p, *w2t_p, *awt_p;
    cudaGetSymbolAddress((void**)&tmp_p, g_tmp);
    cudaGetSymbolAddress((void**)&we_p,  g_we);
    cudaGetSymbolAddress((void**)&q_p,   g_q);
    cudaGetSymbolAddress((void**)&w1t_p, g_W1T);
    cudaGetSymbolAddress((void**)&w2t_p, g_W2T);
    cudaGetSymbolAddress((void**)&awt_p, g_aWT);

    cudaFuncSetAttribute(tf32_gemm<true,  true,  true,  true >, cudaFuncAttributeMaxDynamicSharedMemorySize, SMEM_BYTES);
    cudaFuncSetAttribute(tf32_gemm<false, true,  false, false>, cudaFuncAttributeMaxDynamicSharedMemorySize, SMEM_BYTES);
    cudaFuncSetAttribute(tf32_gemm<false, false, true,  false>, cudaFuncAttributeMaxDynamicSharedMemorySize, SMEM_BYTES);

    // Mask handling
    int* flag_p;
    cudaGetSymbolAddress((void**)&flag_p, g_mask_is32);
    cudaMemsetAsync(flag_p, 0, sizeof(int));
    detect_mask_kernel<<<(NMASK / 2 + 255) / 256, 256>>>((const long long*)mask);
    normalize_mask_kernel<<<(NMASK + 255) / 256, 256>>>(mask);

    // Transpose + tf32-round weights: [K][N] -> [N][K]
    {
        dim3 tb(32, 8);
        dim3 g1((H_SZ + 31) / 32, (D_SZ + 31) / 32);
        dim3 g2((H_SZ + 31) / 32, (H_SZ + 31) / 32);
        transpose_round_kernel<<<g1, tb>>>(W1,     w1t_p, D_SZ, H_SZ);
        transpose_round_kernel<<<g2, tb>>>(W2,     w2t_p, H_SZ, H_SZ);
        transpose_round_kernel<<<g2, tb>>>(attn_W, awt_p, H_SZ, H_SZ);
    }

    dim3 blk(128);
    dim3 grid1(H_SZ / 128, M1 / 128);   // (6, 320)
    dim3 grid3(H_SZ / 128, MQ / 128);   // (6, 64)

    // GEMM1: tmp = round(tanh(WE @ W1 + b1))   [40960 x 768], K=200
    tf32_gemm<true,  true,  true,  true ><<<grid1, blk, SMEM_BYTES>>>(we_in, w1t_p, b1, tmp_p, M1, H_SZ, D_SZ);
    // GEMM2: we = tmp @ W2 + b2                [40960 x 768], K=768 (no cvt)
    tf32_gemm<false, true,  false, false><<<grid1, blk, SMEM_BYTES>>>(tmp_p, w2t_p, b2, we_p, M1, H_SZ, H_SZ);
    // GEMM3: q = lo @ attn_W                   [8192 x 768], K=768
    tf32_gemm<false, false, true,  false><<<grid3, blk, SMEM_BYTES>>>(lo, awt_p, nullptr, q_p, MQ, H_SZ, H_SZ);
    // Fused attention + residual + LayerNorm
    epilogue_kernel<<<MQ, 256>>>(lo, gamma, beta, out);
}

// round 6
// speedup vs baseline: 1.6253x; 1.6253x over previous
#include <cuda_runtime.h>
#include <cuda_bf16.h>
#include <math.h>
#include <stdint.h>

typedef __nv_bfloat16 bf16;

// Problem dimensions (fixed by the reference)
#define B_SZ 16
#define S_SZ 512
#define W_SZ 5
#define D_SZ 200
#define H_SZ 768
#define M1 (B_SZ * S_SZ * W_SZ)   // 40960
#define MQ (B_SZ * S_SZ)          // 8192
#define NMASK (MQ * W_SZ)         // 40960

// Scratch (alloc-free rule: __device__ globals)
__device__ __align__(16) bf16 g_weB [M1 * D_SZ];   // bf16(word_embeddings)
__device__ __align__(16) bf16 g_loB [MQ * H_SZ];   // bf16(layer_output)
__device__ __align__(16) bf16 g_tmpB[M1 * H_SZ];   // bf16(tanh(WE@W1+b1))
__device__ __align__(16) bf16 g_W1T [H_SZ * D_SZ]; // [N][K] bf16
__device__ __align__(16) bf16 g_W2T [H_SZ * H_SZ];
__device__ __align__(16) bf16 g_aWT [H_SZ * H_SZ];
__device__ float g_we[M1 * H_SZ];                  // word_transform out (fp32)
__device__ float g_q [MQ * H_SZ];                  // q (fp32)
__device__ float g_maskf[NMASK];
__device__ int   g_mask_is32;

// ---------------------------------------------------------------------------
// fp32 -> bf16 elementwise (rne)
// ---------------------------------------------------------------------------
__global__ void f32_to_bf16_kernel(const float* __restrict__ in,
                                   bf16* __restrict__ out, int n)
{
    int i = (blockIdx.x * blockDim.x + threadIdx.x) * 4;
    if (i + 3 < n) {
        float4 v = *reinterpret_cast<const float4*>(in + i);
        __nv_bfloat162 p0 = __floats2bfloat162_rn(v.x, v.y);
        __nv_bfloat162 p1 = __floats2bfloat162_rn(v.z, v.w);
        *reinterpret_cast<__nv_bfloat162*>(out + i)     = p0;
        *reinterpret_cast<__nv_bfloat162*>(out + i + 2) = p1;
    } else {
        for (; i < n; i++) out[i] = __float2bfloat16_rn(in[i]);
    }
}

// ---------------------------------------------------------------------------
// Transpose + convert weights: in[K][N] fp32 -> out[N][K] bf16 (rne)
// ---------------------------------------------------------------------------
__global__ void transpose_bf16_kernel(const float* __restrict__ in,
                                      bf16* __restrict__ out,
                                      int K, int N)
{
    __shared__ float tile[32][33];
    int x = blockIdx.x * 32 + threadIdx.x;   // n in input
    int y0 = blockIdx.y * 32;                // k block
    #pragma unroll
    for (int j = 0; j < 32; j += 8) {
        int y = y0 + threadIdx.y + j;
        if (y < K && x < N)
            tile[threadIdx.y + j][threadIdx.x] = in[(size_t)y * N + x];
    }
    __syncthreads();
    int ox = y0 + threadIdx.x;               // k in output
    int oy0 = blockIdx.x * 32;               // n block
    #pragma unroll
    for (int j = 0; j < 32; j += 8) {
        int oy = oy0 + threadIdx.y + j;
        if (oy < N && ox < K)
            out[(size_t)oy * K + ox] =
                __float2bfloat16_rn(tile[threadIdx.x][threadIdx.y + j]);
    }
}

// ---------------------------------------------------------------------------
// Mask dtype detection + normalization (proven since R2)
// ---------------------------------------------------------------------------
__global__ void detect_mask_kernel(const long long* __restrict__ m64)
{
    int i = blockIdx.x * blockDim.x + threadIdx.x;
    if (i < NMASK / 2) {
        unsigned long long v = (unsigned long long)m64[i];
        if (v > 1ULL) atomicOr(&g_mask_is32, 1);
    }
}
__global__ void normalize_mask_kernel(const void* __restrict__ mraw)
{
    int i = blockIdx.x * blockDim.x + threadIdx.x;
    if (i >= NMASK) return;
    float v;
    if (g_mask_is32) v = (float)((const int*)mraw)[i];
    else             v = (float)((const long long*)mraw)[i];
    g_maskf[i] = v;
}

// ---------------------------------------------------------------------------
// BF16 tensor-core GEMM: C[M,N] = op(A[M,K] @ Bt[N,K]^T + bias)
// BM=128, BN=128, BK=64, 128 threads = 4 warps (2x2), warp tile 64x64.
// mma.sync.aligned.m16n8k16.row.col.f32.bf16.bf16.f32, fp32 accumulate.
// A smem [m][k], B smem [n][k], rows padded to 72 bf16 (conflict-free LDS.32).
// ---------------------------------------------------------------------------
#define BKQ 64
#define TSTRIDE 72                       // bf16 elems per smem row
#define TILE_BF (128 * TSTRIDE)          // 9216 bf16 = 18432 B per tile
#define SMEM_BYTES (4 * TILE_BF * 2)     // A0,A1,B0,B1 = 73728 B

__device__ __forceinline__ void cp_async16(uint32_t dst, const void* src, int ssize)
{
    asm volatile("cp.async.cg.shared.global [%0], [%1], 16, %2;\n"
                 :: "r"(dst), "l"(src), "r"(ssize));
}
__device__ __forceinline__ void cp_commit() { asm volatile("cp.async.commit_group;\n"); }
__device__ __forceinline__ void cp_wait0()  { asm volatile("cp.async.wait_group 0;\n"); }

template <bool TANH, bool BIAS, bool OUT_BF16>
__global__ __launch_bounds__(128, 2)
void bf16_gemm(const bf16* __restrict__ A,
               const bf16* __restrict__ Bt,   // [N][K]
               const float* __restrict__ bias,
               void* __restrict__ Cv,
               int M, int N, int K)
{
    extern __shared__ bf16 smem[];
    bf16* As[2] = { smem,                smem + TILE_BF };
    bf16* Bs[2] = { smem + 2 * TILE_BF,  smem + 3 * TILE_BF };

    const int tid  = threadIdx.x;       // 0..127
    const int lane = tid & 31;
    const int wid  = tid >> 5;          // 0..3
    const int wm   = (wid & 1) * 64;
    const int wn   = (wid >> 1) * 64;
    const int g    = lane >> 2;         // 0..7
    const int tg   = lane & 3;          // 0..3
    const int m0   = blockIdx.y * 128;
    const int n0   = blockIdx.x * 128;

    // cp.async coords: tile 128 rows x 64 bf16 -> 1024 16B-chunks, 8/thread
    const int crow = tid >> 3;          // base row (0..15), +16 per i
    const int ac   = (tid & 7) * 8;     // bf16 col of chunk

    uint32_t as_base[2], bs_base[2];
    as_base[0] = (uint32_t)__cvta_generic_to_shared(As[0]);
    as_base[1] = (uint32_t)__cvta_generic_to_shared(As[1]);
    bs_base[0] = (uint32_t)__cvta_generic_to_shared(Bs[0]);
    bs_base[1] = (uint32_t)__cvta_generic_to_shared(Bs[1]);

    float acc[4][8][4];
    #pragma unroll
    for (int mi = 0; mi < 4; mi++)
        #pragma unroll
        for (int ni = 0; ni < 8; ni++)
            #pragma unroll
            for (int r = 0; r < 4; r++)
                acc[mi][ni][r] = 0.f;

    const int tiles = (K + BKQ - 1) / BKQ;

    auto load_tile = [&](int buf, int k0) {
        int gk = k0 + ac;
        int ok = (gk < K) ? 16 : 0;     // K % 8 == 0 for all our K
        int gks = ok ? gk : 0;
        #pragma unroll
        for (int i = 0; i < 8; i++) {
            int row = crow + 16 * i;
            cp_async16(as_base[buf] + (row * TSTRIDE + ac) * 2,
                       A + (size_t)(m0 + row) * K + gks, ok);
        }
        #pragma unroll
        for (int i = 0; i < 8; i++) {
            int row = crow + 16 * i;
            cp_async16(bs_base[buf] + (row * TSTRIDE + ac) * 2,
                       Bt + (size_t)(n0 + row) * K + gks, ok);
        }
        cp_commit();
    };

    load_tile(0, 0);

    int buf = 0;
    for (int t = 0; t < tiles; t++) {
        cp_wait0();
        __syncthreads();
        if (t + 1 < tiles)
            load_tile(buf ^ 1, (t + 1) * BKQ);

        const bf16* Ab = As[buf];
        const bf16* Bb = Bs[buf];

        #pragma unroll
        for (int s = 0; s < BKQ / 16; s++) {
            const int kb = s * 16;
            // A fragments: m16n8k16 row-major; each reg = 2 consecutive k's
            uint32_t af[4][4];
            #pragma unroll
            for (int mi = 0; mi < 4; mi++) {
                const bf16* p = Ab + (wm + mi * 16 + g) * TSTRIDE + kb + 2 * tg;
                af[mi][0] = *reinterpret_cast<const uint32_t*>(p);
                af[mi][1] = *reinterpret_cast<const uint32_t*>(p + 8 * TSTRIDE);
                af[mi][2] = *reinterpret_cast<const uint32_t*>(p + 8);
                af[mi][3] = *reinterpret_cast<const uint32_t*>(p + 8 * TSTRIDE + 8);
            }
            // B fragments from [n][k] smem
            uint32_t bfr[8][2];
            #pragma unroll
            for (int ni = 0; ni < 8; ni++) {
                const bf16* p = Bb + (wn + ni * 8 + g) * TSTRIDE + kb + 2 * tg;
                bfr[ni][0] = *reinterpret_cast<const uint32_t*>(p);
                bfr[ni][1] = *reinterpret_cast<const uint32_t*>(p + 8);
            }
            #pragma unroll
            for (int mi = 0; mi < 4; mi++)
                #pragma unroll
                for (int ni = 0; ni < 8; ni++) {
                    asm volatile(
                        "mma.sync.aligned.m16n8k16.row.col.f32.bf16.bf16.f32 "
                        "{%0,%1,%2,%3}, {%4,%5,%6,%7}, {%8,%9}, {%0,%1,%2,%3};\n"
                        : "+f"(acc[mi][ni][0]), "+f"(acc[mi][ni][1]),
                          "+f"(acc[mi][ni][2]), "+f"(acc[mi][ni][3])
                        : "r"(af[mi][0]), "r"(af[mi][1]), "r"(af[mi][2]), "r"(af[mi][3]),
                          "r"(bfr[ni][0]), "r"(bfr[ni][1]));
                }
        }
        buf ^= 1;
    }

    // epilogue
    #pragma unroll
    for (int ni = 0; ni < 8; ni++) {
        const int col = n0 + wn + ni * 8 + tg * 2;
        float b0 = 0.f, b1 = 0.f;
        if (BIAS) { b0 = bias[col]; b1 = bias[col + 1]; }
        #pragma unroll
        for (int mi = 0; mi < 4; mi++) {
            const int row = m0 + wm + mi * 16 + g;
            float r0 = acc[mi][ni][0] + b0;
            float r1 = acc[mi][ni][1] + b1;
            float r2 = acc[mi][ni][2] + b0;
            float r3 = acc[mi][ni][3] + b1;
            if (TANH) { r0 = tanhf(r0); r1 = tanhf(r1); r2 = tanhf(r2); r3 = tanhf(r3); }
            if (OUT_BF16) {
                bf16* C = (bf16*)Cv;
                *reinterpret_cast<__nv_bfloat162*>(&C[(size_t)row * N + col]) =
                    __floats2bfloat162_rn(r0, r1);
                *reinterpret_cast<__nv_bfloat162*>(&C[(size_t)(row + 8) * N + col]) =
                    __floats2bfloat162_rn(r2, r3);
            } else {
                float* C = (float*)Cv;
                *reinterpret_cast<float2*>(&C[(size_t)row * N + col])       = make_float2(r0, r1);
                *reinterpret_cast<float2*>(&C[(size_t)(row + 8) * N + col]) = make_float2(r2, r3);
            }
        }
    }
}

// ---------------------------------------------------------------------------
// Fused epilogue (unchanged, proven since R2)
// ---------------------------------------------------------------------------
__global__ __launch_bounds__(256)
void epilogue_kernel(const float* __restrict__ lo,
                     const float* __restrict__ gamma,
                     const float* __restrict__ beta,
                     float* __restrict__ out)
{
    const int bs  = blockIdx.x;
    const int tid = threadIdx.x;

    __shared__ float red[5][256];
    __shared__ float s_alpha[5];

    const float* qrow  = g_q  + (size_t)bs * H_SZ;
    const float* werow = g_we + (size_t)bs * W_SZ * H_SZ;
    const float* lorow = lo   + (size_t)bs * H_SZ;

    float qv[3], lov[3], wev[5][3];
    #pragma unroll
    for (int e = 0; e < 3; e++) {
        int h = tid + e * 256;
        qv[e]  = qrow[h];
        lov[e] = lorow[h];
        #pragma unroll
        for (int w = 0; w < W_SZ; w++)
            wev[w][e] = werow[w * H_SZ + h];
    }

    #pragma unroll
    for (int w = 0; w < W_SZ; w++) {
        float d = 0.f;
        #pragma unroll
        for (int e = 0; e < 3; e++)
            d = fmaf(qv[e], wev[w][e], d);
        red[w][tid] = d;
    }
    __syncthreads();
    for (int s = 128; s > 0; s >>= 1) {
        if (tid < s) {
            #pragma unroll
            for (int w = 0; w < W_SZ; w++)
                red[w][tid] += red[w][tid + s];
        }
        __syncthreads();
    }

    if (tid == 0) {
        float sc[5];
        float mx = -1e30f;
        #pragma unroll
        for (int w = 0; w < W_SZ; w++) {
            float mk = g_maskf[(size_t)bs * W_SZ + w];
            sc[w] = red[w][0] + (1.f - mk) * (-10000.f);
            mx = fmaxf(mx, sc[w]);
        }
        float sum = 0.f;
        #pragma unroll
        for (int w = 0; w < W_SZ; w++) {
            sc[w] = expf(sc[w] - mx);
            sum += sc[w];
        }
        float inv = 1.f / sum;
        #pragma unroll
        for (int w = 0; w < W_SZ; w++)
            s_alpha[w] = sc[w] * inv;
    }
    __syncthreads();

    float alpha[5];
    #pragma unroll
    for (int w = 0; w < W_SZ; w++) alpha[w] = s_alpha[w];

    float hv[3];
    float psum = 0.f, psq = 0.f;
    #pragma unroll
    for (int e = 0; e < 3; e++) {
        float agg = 0.f;
        #pragma unroll
        for (int w = 0; w < W_SZ; w++)
            agg = fmaf(alpha[w], wev[w][e], agg);
        hv[e] = lov[e] + agg;
        psum += hv[e];
        psq  = fmaf(hv[e], hv[e], psq);
    }
    __syncthreads();
    red[0][tid] = psum;
    red[1][tid] = psq;
    __syncthreads();
    for (int s = 128; s > 0; s >>= 1) {
        if (tid < s) {
            red[0][tid] += red[0][tid + s];
            red[1][tid] += red[1][tid + s];
        }
        __syncthreads();
    }

    const float inv_h = 1.f / (float)H_SZ;
    float mu   = red[0][0] * inv_h;
    float var  = red[1][0] * inv_h - mu * mu;
    float rstd = rsqrtf(var + 1e-12f);

    #pragma unroll
    for (int e = 0; e < 3; e++) {
        int h = tid + e * 256;
        out[(size_t)bs * H_SZ + h] = (hv[e] - mu) * rstd * gamma[h] + beta[h];
    }
}

// ---------------------------------------------------------------------------
// Launch
// ---------------------------------------------------------------------------
extern "C" void kernel_launch(void* const* d_in, const int* in_sizes, int n_in,
                              void* d_out, int out_size)
{
    const float* lo     = (const float*)d_in[0];
    const float* we_in  = (const float*)d_in[1];
    const void*  mask   = d_in[2];
    const float* W1     = (const float*)d_in[3];
    const float* b1     = (const float*)d_in[4];
    const float* W2     = (const float*)d_in[5];
    const float* b2     = (const float*)d_in[6];
    const float* attn_W = (const float*)d_in[7];
    const float* gamma  = (const float*)d_in[8];
    const float* beta   = (const float*)d_in[9];
    float*       out    = (float*)d_out;

    bf16 *weB_p, *loB_p, *tmpB_p, *w1t_p, *w2t_p, *awt_p;
    float *we_p, *q_p;
    cudaGetSymbolAddress((void**)&weB_p,  g_weB);
    cudaGetSymbolAddress((void**)&loB_p,  g_loB);
    cudaGetSymbolAddress((void**)&tmpB_p, g_tmpB);
    cudaGetSymbolAddress((void**)&w1t_p,  g_W1T);
    cudaGetSymbolAddress((void**)&w2t_p,  g_W2T);
    cudaGetSymbolAddress((void**)&awt_p,  g_aWT);
    cudaGetSymbolAddress((void**)&we_p,   g_we);
    cudaGetSymbolAddress((void**)&q_p,    g_q);

    cudaFuncSetAttribute(bf16_gemm<true,  true,  true >, cudaFuncAttributeMaxDynamicSharedMemorySize, SMEM_BYTES);
    cudaFuncSetAttribute(bf16_gemm<false, true,  false>, cudaFuncAttributeMaxDynamicSharedMemorySize, SMEM_BYTES);
    cudaFuncSetAttribute(bf16_gemm<false, false, false>, cudaFuncAttributeMaxDynamicSharedMemorySize, SMEM_BYTES);

    // Mask handling
    int* flag_p;
    cudaGetSymbolAddress((void**)&flag_p, g_mask_is32);
    cudaMemsetAsync(flag_p, 0, sizeof(int));
    detect_mask_kernel<<<(NMASK / 2 + 255) / 256, 256>>>((const long long*)mask);
    normalize_mask_kernel<<<(NMASK + 255) / 256, 256>>>(mask);

    // Pre-convert activations to bf16
    f32_to_bf16_kernel<<<(M1 * D_SZ / 4 + 255) / 256, 256>>>(we_in, weB_p, M1 * D_SZ);
    f32_to_bf16_kernel<<<(MQ * H_SZ / 4 + 255) / 256, 256>>>(lo,    loB_p, MQ * H_SZ);

    // Transpose + convert weights: [K][N] fp32 -> [N][K] bf16
    {
        dim3 tb(32, 8);
        dim3 g1((H_SZ + 31) / 32, (D_SZ + 31) / 32);
        dim3 g2((H_SZ + 31) / 32, (H_SZ + 31) / 32);
        transpose_bf16_kernel<<<g1, tb>>>(W1,     w1t_p, D_SZ, H_SZ);
        transpose_bf16_kernel<<<g2, tb>>>(W2,     w2t_p, H_SZ, H_SZ);
        transpose_bf16_kernel<<<g2, tb>>>(attn_W, awt_p, H_SZ, H_SZ);
    }

    dim3 blk(128);
    dim3 grid1(H_SZ / 128, M1 / 128);   // (6, 320)
    dim3 grid3(H_SZ / 128, MQ / 128);   // (6, 64)

    // GEMM1: tmpB = bf16(tanh(WE @ W1 + b1))   [40960 x 768], K=200
    bf16_gemm<true,  true,  true ><<<grid1, blk, SMEM_BYTES>>>(weB_p, w1t_p, b1, tmpB_p, M1, H_SZ, D_SZ);
    // GEMM2: we = tmpB @ W2 + b2 (fp32 out)    [40960 x 768], K=768
    bf16_gemm<false, true,  false><<<grid1, blk, SMEM_BYTES>>>(tmpB_p, w2t_p, b2, we_p, M1, H_SZ, H_SZ);
    // GEMM3: q = loB @ attn_W (fp32 out)       [8192 x 768], K=768
    bf16_gemm<false, false, false><<<grid3, blk, SMEM_BYTES>>>(loB_p, awt_p, nullptr, q_p, MQ, H_SZ, H_SZ);
    // Fused attention + residual + LayerNorm
    epilogue_kernel<<<MQ, 256>>>(lo, gamma, beta, out);
}

// round 8
// speedup vs baseline: 2.0564x; 1.2653x over previous
#include <cuda_runtime.h>
#include <cuda_bf16.h>
#include <math.h>
#include <stdint.h>

typedef __nv_bfloat16 bf16;

// Problem dimensions (fixed by the reference)
#define B_SZ 16
#define S_SZ 512
#define W_SZ 5
#define D_SZ 200
#define H_SZ 768
#define M1 (B_SZ * S_SZ * W_SZ)   // 40960
#define MQ (B_SZ * S_SZ)          // 8192
#define NMASK (MQ * W_SZ)         // 40960

// Scratch (alloc-free rule: __device__ globals)
__device__ __align__(16) bf16 g_weB [M1 * D_SZ];   // bf16(word_embeddings)
__device__ __align__(16) bf16 g_loB [MQ * H_SZ];   // bf16(layer_output)
__device__ __align__(16) bf16 g_tmpB[M1 * H_SZ];   // bf16(tanh(WE@W1+b1))
__device__ __align__(16) bf16 g_qB  [MQ * H_SZ];   // bf16(lo @ attn_W)
__device__ __align__(16) bf16 g_ctxB[MQ * H_SZ];   // bf16(sum_w alpha_w tmp_w)
__device__ __align__(16) bf16 g_W1T [H_SZ * D_SZ]; // [N][K] bf16
__device__ __align__(16) bf16 g_W2B [H_SZ * H_SZ]; // W2 as-is ([h][k]) bf16
__device__ __align__(16) bf16 g_W2T [H_SZ * H_SZ]; // W2 transposed ([k][h]) bf16
__device__ __align__(16) bf16 g_aWT [H_SZ * H_SZ]; // attn_W transposed bf16
__device__ float g_r  [MQ * H_SZ];                 // r = q @ W2^T (fp32)
__device__ float g_agg[MQ * H_SZ];                 // ctx @ W2 + b2 (fp32)
__device__ float g_maskf[NMASK];
__device__ int   g_mask_is32;

// ---------------------------------------------------------------------------
// fp32 -> bf16 elementwise (rne)
// ---------------------------------------------------------------------------
__global__ void f32_to_bf16_kernel(const float* __restrict__ in,
                                   bf16* __restrict__ out, int n)
{
    int i = (blockIdx.x * blockDim.x + threadIdx.x) * 4;
    if (i + 3 < n) {
        float4 v = *reinterpret_cast<const float4*>(in + i);
        __nv_bfloat162 p0 = __floats2bfloat162_rn(v.x, v.y);
        __nv_bfloat162 p1 = __floats2bfloat162_rn(v.z, v.w);
        *reinterpret_cast<__nv_bfloat162*>(out + i)     = p0;
        *reinterpret_cast<__nv_bfloat162*>(out + i + 2) = p1;
    } else {
        for (; i < n; i++) out[i] = __float2bfloat16_rn(in[i]);
    }
}

// ---------------------------------------------------------------------------
// Transpose + convert weights: in[K][N] fp32 -> out[N][K] bf16 (rne)
// ---------------------------------------------------------------------------
__global__ void transpose_bf16_kernel(const float* __restrict__ in,
                                      bf16* __restrict__ out,
                                      int K, int N)
{
    __shared__ float tile[32][33];
    int x = blockIdx.x * 32 + threadIdx.x;
    int y0 = blockIdx.y * 32;
    #pragma unroll
    for (int j = 0; j < 32; j += 8) {
        int y = y0 + threadIdx.y + j;
        if (y < K && x < N)
            tile[threadIdx.y + j][threadIdx.x] = in[(size_t)y * N + x];
    }
    __syncthreads();
    int ox = y0 + threadIdx.x;
    int oy0 = blockIdx.x * 32;
    #pragma unroll
    for (int j = 0; j < 32; j += 8) {
        int oy = oy0 + threadIdx.y + j;
        if (oy < N && ox < K)
            out[(size_t)oy * K + ox] =
                __float2bfloat16_rn(tile[threadIdx.x][threadIdx.y + j]);
    }
}

// ---------------------------------------------------------------------------
// Mask dtype detection + normalization (proven since R2)
// ---------------------------------------------------------------------------
__global__ void detect_mask_kernel(const long long* __restrict__ m64)
{
    int i = blockIdx.x * blockDim.x + threadIdx.x;
    if (i < NMASK / 2) {
        unsigned long long v = (unsigned long long)m64[i];
        if (v > 1ULL) atomicOr(&g_mask_is32, 1);
    }
}
__global__ void normalize_mask_kernel(const void* __restrict__ mraw)
{
    int i = blockIdx.x * blockDim.x + threadIdx.x;
    if (i >= NMASK) return;
    float v;
    if (g_mask_is32) v = (float)((const int*)mraw)[i];
    else             v = (float)((const long long*)mraw)[i];
    g_maskf[i] = v;
}

// ---------------------------------------------------------------------------
// BF16 tensor-core GEMM (proven R6): C[M,N] = op(A[M,K] @ Bt[N,K]^T + bias)
// BM=128, BN=128, BK=64, 128 threads = 4 warps (2x2), warp tile 64x64.
// ---------------------------------------------------------------------------
#define BKQ 64
#define TSTRIDE 72
#define TILE_BF (128 * TSTRIDE)
#define SMEM_BYTES (4 * TILE_BF * 2)     // 73728 B

__device__ __forceinline__ void cp_async16(uint32_t dst, const void* src, int ssize)
{
    asm volatile("cp.async.cg.shared.global [%0], [%1], 16, %2;\n"
                 :: "r"(dst), "l"(src), "r"(ssize));
}
__device__ __forceinline__ void cp_commit() { asm volatile("cp.async.commit_group;\n"); }
__device__ __forceinline__ void cp_wait0()  { asm volatile("cp.async.wait_group 0;\n"); }

template <bool TANH, bool BIAS, bool OUT_BF16>
__global__ __launch_bounds__(128, 2)
void bf16_gemm(const bf16* __restrict__ A,
               const bf16* __restrict__ Bt,   // [N][K]
               const float* __restrict__ bias,
               void* __restrict__ Cv,
               int M, int N, int K)
{
    extern __shared__ bf16 smem[];
    bf16* As[2] = { smem,                smem + TILE_BF };
    bf16* Bs[2] = { smem + 2 * TILE_BF,  smem + 3 * TILE_BF };

    const int tid  = threadIdx.x;
    const int lane = tid & 31;
    const int wid  = tid >> 5;
    const int wm   = (wid & 1) * 64;
    const int wn   = (wid >> 1) * 64;
    const int g    = lane >> 2;
    const int tg   = lane & 3;
    const int m0   = blockIdx.y * 128;
    const int n0   = blockIdx.x * 128;

    const int crow = tid >> 3;
    const int ac   = (tid & 7) * 8;

    uint32_t as_base[2], bs_base[2];
    as_base[0] = (uint32_t)__cvta_generic_to_shared(As[0]);
    as_base[1] = (uint32_t)__cvta_generic_to_shared(As[1]);
    bs_base[0] = (uint32_t)__cvta_generic_to_shared(Bs[0]);
    bs_base[1] = (uint32_t)__cvta_generic_to_shared(Bs[1]);

    float acc[4][8][4];
    #pragma unroll
    for (int mi = 0; mi < 4; mi++)
        #pragma unroll
        for (int ni = 0; ni < 8; ni++)
            #pragma unroll
            for (int r = 0; r < 4; r++)
                acc[mi][ni][r] = 0.f;

    const int tiles = (K + BKQ - 1) / BKQ;

    auto load_tile = [&](int buf, int k0) {
        int gk = k0 + ac;
        int ok = (gk < K) ? 16 : 0;
        int gks = ok ? gk : 0;
        #pragma unroll
        for (int i = 0; i < 8; i++) {
            int row = crow + 16 * i;
            cp_async16(as_base[buf] + (row * TSTRIDE + ac) * 2,
                       A + (size_t)(m0 + row) * K + gks, ok);
        }
        #pragma unroll
        for (int i = 0; i < 8; i++) {
            int row = crow + 16 * i;
            cp_async16(bs_base[buf] + (row * TSTRIDE + ac) * 2,
                       Bt + (size_t)(n0 + row) * K + gks, ok);
        }
        cp_commit();
    };

    load_tile(0, 0);

    int buf = 0;
    for (int t = 0; t < tiles; t++) {
        cp_wait0();
        __syncthreads();
        if (t + 1 < tiles)
            load_tile(buf ^ 1, (t + 1) * BKQ);

        const bf16* Ab = As[buf];
        const bf16* Bb = Bs[buf];

        #pragma unroll
        for (int s = 0; s < BKQ / 16; s++) {
            const int kb = s * 16;
            uint32_t af[4][4];
            #pragma unroll
            for (int mi = 0; mi < 4; mi++) {
                const bf16* p = Ab + (wm + mi * 16 + g) * TSTRIDE + kb + 2 * tg;
                af[mi][0] = *reinterpret_cast<const uint32_t*>(p);
                af[mi][1] = *reinterpret_cast<const uint32_t*>(p + 8 * TSTRIDE);
                af[mi][2] = *reinterpret_cast<const uint32_t*>(p + 8);
                af[mi][3] = *reinterpret_cast<const uint32_t*>(p + 8 * TSTRIDE + 8);
            }
            uint32_t bfr[8][2];
            #pragma unroll
            for (int ni = 0; ni < 8; ni++) {
                const bf16* p = Bb + (wn + ni * 8 + g) * TSTRIDE + kb + 2 * tg;
                bfr[ni][0] = *reinterpret_cast<const uint32_t*>(p);
                bfr[ni][1] = *reinterpret_cast<const uint32_t*>(p + 8);
            }
            #pragma unroll
            for (int mi = 0; mi < 4; mi++)
                #pragma unroll
                for (int ni = 0; ni < 8; ni++) {
                    asm volatile(
                        "mma.sync.aligned.m16n8k16.row.col.f32.bf16.bf16.f32 "
                        "{%0,%1,%2,%3}, {%4,%5,%6,%7}, {%8,%9}, {%0,%1,%2,%3};\n"
                        : "+f"(acc[mi][ni][0]), "+f"(acc[mi][ni][1]),
                          "+f"(acc[mi][ni][2]), "+f"(acc[mi][ni][3])
                        : "r"(af[mi][0]), "r"(af[mi][1]), "r"(af[mi][2]), "r"(af[mi][3]),
                          "r"(bfr[ni][0]), "r"(bfr[ni][1]));
                }
        }
        buf ^= 1;
    }

    #pragma unroll
    for (int ni = 0; ni < 8; ni++) {
        const int col = n0 + wn + ni * 8 + tg * 2;
        float b0 = 0.f, b1 = 0.f;
        if (BIAS) { b0 = bias[col]; b1 = bias[col + 1]; }
        #pragma unroll
        for (int mi = 0; mi < 4; mi++) {
            const int row = m0 + wm + mi * 16 + g;
            float r0 = acc[mi][ni][0] + b0;
            float r1 = acc[mi][ni][1] + b1;
            float r2 = acc[mi][ni][2] + b0;
            float r3 = acc[mi][ni][3] + b1;
            if (TANH) { r0 = tanhf(r0); r1 = tanhf(r1); r2 = tanhf(r2); r3 = tanhf(r3); }
            if (OUT_BF16) {
                bf16* C = (bf16*)Cv;
                *reinterpret_cast<__nv_bfloat162*>(&C[(size_t)row * N + col]) =
                    __floats2bfloat162_rn(r0, r1);
                *reinterpret_cast<__nv_bfloat162*>(&C[(size_t)(row + 8) * N + col]) =
                    __floats2bfloat162_rn(r2, r3);
            } else {
                float* C = (float*)Cv;
                *reinterpret_cast<float2*>(&C[(size_t)row * N + col])       = make_float2(r0, r1);
                *reinterpret_cast<float2*>(&C[(size_t)(row + 8) * N + col]) = make_float2(r2, r3);
            }
        }
    }
}

// ---------------------------------------------------------------------------
// Attention kernel: per token bs:
//   score_w = <r_bs, tmp_{bs,w}>;  masked softmax over W=5;
//   ctx_bs = sum_w alpha_w * tmp_{bs,w}  -> bf16
// One block of 256 threads per token; each thread owns 3 H-elements.
// ---------------------------------------------------------------------------
__global__ __launch_bounds__(256)
void attn_kernel(bf16* __restrict__ ctxB)
{
    const int bs  = blockIdx.x;
    const int tid = threadIdx.x;

    __shared__ float red[5][256];
    __shared__ float s_alpha[5];

    const float* rrow  = g_r    + (size_t)bs * H_SZ;
    const bf16*  trow  = g_tmpB + (size_t)bs * W_SZ * H_SZ;

    float rv[3], tv[5][3];
    #pragma unroll
    for (int e = 0; e < 3; e++) {
        int h = tid + e * 256;
        rv[e] = rrow[h];
        #pragma unroll
        for (int w = 0; w < W_SZ; w++)
            tv[w][e] = __bfloat162float(trow[w * H_SZ + h]);
    }

    #pragma unroll
    for (int w = 0; w < W_SZ; w++) {
        float d = 0.f;
        #pragma unroll
        for (int e = 0; e < 3; e++)
            d = fmaf(rv[e], tv[w][e], d);
        red[w][tid] = d;
    }
    __syncthreads();
    for (int s = 128; s > 0; s >>= 1) {
        if (tid < s) {
            #pragma unroll
            for (int w = 0; w < W_SZ; w++)
                red[w][tid] += red[w][tid + s];
        }
        __syncthreads();
    }

    if (tid == 0) {
        float sc[5];
        float mx = -1e30f;
        #pragma unroll
        for (int w = 0; w < W_SZ; w++) {
            float mk = g_maskf[(size_t)bs * W_SZ + w];
            sc[w] = red[w][0] + (1.f - mk) * (-10000.f);
            mx = fmaxf(mx, sc[w]);
        }
        float sum = 0.f;
        #pragma unroll
        for (int w = 0; w < W_SZ; w++) {
            sc[w] = expf(sc[w] - mx);
            sum += sc[w];
        }
        float inv = 1.f / sum;
        #pragma unroll
        for (int w = 0; w < W_SZ; w++)
            s_alpha[w] = sc[w] * inv;
    }
    __syncthreads();

    float alpha[5];
    #pragma unroll
    for (int w = 0; w < W_SZ; w++) alpha[w] = s_alpha[w];

    #pragma unroll
    for (int e = 0; e < 3; e++) {
        int h = tid + e * 256;
        float c = 0.f;
        #pragma unroll
        for (int w = 0; w < W_SZ; w++)
            c = fmaf(alpha[w], tv[w][e], c);
        ctxB[(size_t)bs * H_SZ + h] = __float2bfloat16_rn(c);
    }
}

// ---------------------------------------------------------------------------
// Residual + LayerNorm: out = LN(lo + agg) * gamma + beta
// ---------------------------------------------------------------------------
__global__ __launch_bounds__(256)
void ln_kernel(const float* __restrict__ lo,
               const float* __restrict__ gamma,
               const float* __restrict__ beta,
               float* __restrict__ out)
{
    const int bs  = blockIdx.x;
    const int tid = threadIdx.x;

    __shared__ float red0[256], red1[256];

    const float* lorow = lo    + (size_t)bs * H_SZ;
    const float* agrow = g_agg + (size_t)bs * H_SZ;

    float hv[3];
    float psum = 0.f, psq = 0.f;
    #pragma unroll
    for (int e = 0; e < 3; e++) {
        int h = tid + e * 256;
        hv[e] = lorow[h] + agrow[h];
        psum += hv[e];
        psq  = fmaf(hv[e], hv[e], psq);
    }
    red0[tid] = psum;
    red1[tid] = psq;
    __syncthreads();
    for (int s = 128; s > 0; s >>= 1) {
        if (tid < s) {
            red0[tid] += red0[tid + s];
            red1[tid] += red1[tid + s];
        }
        __syncthreads();
    }

    const float inv_h = 1.f / (float)H_SZ;
    float mu   = red0[0] * inv_h;
    float var  = red1[0] * inv_h - mu * mu;
    float rstd = rsqrtf(var + 1e-12f);

    #pragma unroll
    for (int e = 0; e < 3; e++) {
        int h = tid + e * 256;
        out[(size_t)bs * H_SZ + h] = (hv[e] - mu) * rstd * gamma[h] + beta[h];
    }
}

// ---------------------------------------------------------------------------
// Launch
// ---------------------------------------------------------------------------
extern "C" void kernel_launch(void* const* d_in, const int* in_sizes, int n_in,
                              void* d_out, int out_size)
{
    const float* lo     = (const float*)d_in[0];
    const float* we_in  = (const float*)d_in[1];
    const void*  mask   = d_in[2];
    const float* W1     = (const float*)d_in[3];
    const float* b1     = (const float*)d_in[4];
    const float* W2     = (const float*)d_in[5];
    const float* b2     = (const float*)d_in[6];
    const float* attn_W = (const float*)d_in[7];
    const float* gamma  = (const float*)d_in[8];
    const float* beta   = (const float*)d_in[9];
    float*       out    = (float*)d_out;

    bf16 *weB_p, *loB_p, *tmpB_p, *qB_p, *ctxB_p, *w1t_p, *w2b_p, *w2t_p, *awt_p;
    float *r_p, *agg_p;
    cudaGetSymbolAddress((void**)&weB_p,  g_weB);
    cudaGetSymbolAddress((void**)&loB_p,  g_loB);
    cudaGetSymbolAddress((void**)&tmpB_p, g_tmpB);
    cudaGetSymbolAddress((void**)&qB_p,   g_qB);
    cudaGetSymbolAddress((void**)&ctxB_p, g_ctxB);
    cudaGetSymbolAddress((void**)&w1t_p,  g_W1T);
    cudaGetSymbolAddress((void**)&w2b_p,  g_W2B);
    cudaGetSymbolAddress((void**)&w2t_p,  g_W2T);
    cudaGetSymbolAddress((void**)&awt_p,  g_aWT);
    cudaGetSymbolAddress((void**)&r_p,    g_r);
    cudaGetSymbolAddress((void**)&agg_p,  g_agg);

    cudaFuncSetAttribute(bf16_gemm<true,  true,  true >, cudaFuncAttributeMaxDynamicSharedMemorySize, SMEM_BYTES);
    cudaFuncSetAttribute(bf16_gemm<false, false, true >, cudaFuncAttributeMaxDynamicSharedMemorySize, SMEM_BYTES);
    cudaFuncSetAttribute(bf16_gemm<false, false, false>, cudaFuncAttributeMaxDynamicSharedMemorySize, SMEM_BYTES);
    cudaFuncSetAttribute(bf16_gemm<false, true,  false>, cudaFuncAttributeMaxDynamicSharedMemorySize, SMEM_BYTES);

    // Mask handling
    int* flag_p;
    cudaGetSymbolAddress((void**)&flag_p, g_mask_is32);
    cudaMemsetAsync(flag_p, 0, sizeof(int));
    detect_mask_kernel<<<(NMASK / 2 + 255) / 256, 256>>>((const long long*)mask);
    normalize_mask_kernel<<<(NMASK + 255) / 256, 256>>>(mask);

    // Pre-convert activations + W2 (as-is) to bf16
    f32_to_bf16_kernel<<<(M1 * D_SZ / 4 + 255) / 256, 256>>>(we_in, weB_p, M1 * D_SZ);
    f32_to_bf16_kernel<<<(MQ * H_SZ / 4 + 255) / 256, 256>>>(lo,    loB_p, MQ * H_SZ);
    f32_to_bf16_kernel<<<(H_SZ * H_SZ / 4 + 255) / 256, 256>>>(W2,  w2b_p, H_SZ * H_SZ);

    // Transpose + convert weights: [K][N] fp32 -> [N][K] bf16
    {
        dim3 tb(32, 8);
        dim3 g1((H_SZ + 31) / 32, (D_SZ + 31) / 32);
        dim3 g2((H_SZ + 31) / 32, (H_SZ + 31) / 32);
        transpose_bf16_kernel<<<g1, tb>>>(W1,     w1t_p, D_SZ, H_SZ);
        transpose_bf16_kernel<<<g2, tb>>>(W2,     w2t_p, H_SZ, H_SZ);
        transpose_bf16_kernel<<<g2, tb>>>(attn_W, awt_p, H_SZ, H_SZ);
    }

    dim3 blk(128);
    dim3 grid1(H_SZ / 128, M1 / 128);   // (6, 320)
    dim3 gridQ(H_SZ / 128, MQ / 128);   // (6, 64)

    // GEMM1: tmpB = bf16(tanh(WE @ W1 + b1))      [40960 x 768], K=200
    bf16_gemm<true,  true,  true ><<<grid1, blk, SMEM_BYTES>>>(weB_p, w1t_p, b1, tmpB_p, M1, H_SZ, D_SZ);
    // GEMM3: qB = bf16(lo @ attn_W)               [8192 x 768], K=768
    bf16_gemm<false, false, true ><<<gridQ, blk, SMEM_BYTES>>>(loB_p, awt_p, nullptr, qB_p, MQ, H_SZ, H_SZ);
    // GEMM_r: r = qB @ W2^T  (Bt = W2 as-is [h][k]) [8192 x 768], K=768, fp32 out
    bf16_gemm<false, false, false><<<gridQ, blk, SMEM_BYTES>>>(qB_p, w2b_p, nullptr, r_p, MQ, H_SZ, H_SZ);
    // Attention: scores via <r, tmp_w>, softmax, ctx = sum alpha_w tmp_w (bf16)
    attn_kernel<<<MQ, 256>>>(ctxB_p);
    // GEMM_agg: agg = ctx @ W2 + b2  (Bt = W2T [k][h]) [8192 x 768], K=768, fp32 out
    bf16_gemm<false, true,  false><<<gridQ, blk, SMEM_BYTES>>>(ctxB_p, w2t_p, b2, agg_p, MQ, H_SZ, H_SZ);
    // Residual + LayerNorm
    ln_kernel<<<MQ, 256>>>(lo, gamma, beta, out);
}

// round 9
// speedup vs baseline: 2.2574x; 1.0977x over previous
#include <cuda_runtime.h>
#include <cuda_bf16.h>
#include <math.h>
#include <stdint.h>

typedef __nv_bfloat16 bf16;

// Problem dimensions (fixed by the reference)
#define B_SZ 16
#define S_SZ 512
#define W_SZ 5
#define D_SZ 200
#define H_SZ 768
#define M1 (B_SZ * S_SZ * W_SZ)   // 40960
#define MQ (B_SZ * S_SZ)          // 8192
#define NMASK (MQ * W_SZ)         // 40960

// Scratch (alloc-free rule: __device__ globals)
__device__ __align__(16) bf16 g_weB [M1 * D_SZ];   // bf16(word_embeddings)
__device__ __align__(16) bf16 g_loB [MQ * H_SZ];   // bf16(layer_output)
__device__ __align__(16) bf16 g_tmpB[M1 * H_SZ];   // bf16(tanh(WE@W1+b1))
__device__ __align__(16) bf16 g_ctxB[MQ * H_SZ];   // bf16(sum_w alpha_w tmp_w)
__device__ __align__(16) bf16 g_W1T [H_SZ * D_SZ]; // [N][K] bf16
__device__ __align__(16) bf16 g_W2B [H_SZ * H_SZ]; // W2 as-is bf16
__device__ __align__(16) bf16 g_W2T [H_SZ * H_SZ]; // W2 transposed bf16
__device__ __align__(16) bf16 g_aWB [H_SZ * H_SZ]; // attn_W as-is bf16
__device__ __align__(16) bf16 g_WcT [H_SZ * H_SZ]; // WcT[n][k] = sum_h W2[n][h] attn_W[k][h]
__device__ float g_r  [MQ * H_SZ];                 // r = lo @ Wc (fp32)
__device__ float g_agg[MQ * H_SZ];                 // ctx @ W2 + b2 (fp32)
__device__ float g_maskf[NMASK];
__device__ int   g_mask_is32;

// ---------------------------------------------------------------------------
// fp32 -> bf16 elementwise (rne)
// ---------------------------------------------------------------------------
__global__ void f32_to_bf16_kernel(const float* __restrict__ in,
                                   bf16* __restrict__ out, int n)
{
    int i = (blockIdx.x * blockDim.x + threadIdx.x) * 4;
    if (i + 3 < n) {
        float4 v = *reinterpret_cast<const float4*>(in + i);
        __nv_bfloat162 p0 = __floats2bfloat162_rn(v.x, v.y);
        __nv_bfloat162 p1 = __floats2bfloat162_rn(v.z, v.w);
        *reinterpret_cast<__nv_bfloat162*>(out + i)     = p0;
        *reinterpret_cast<__nv_bfloat162*>(out + i + 2) = p1;
    } else {
        for (; i < n; i++) out[i] = __float2bfloat16_rn(in[i]);
    }
}

// ---------------------------------------------------------------------------
// Transpose + convert weights: in[K][N] fp32 -> out[N][K] bf16 (rne)
// ---------------------------------------------------------------------------
__global__ void transpose_bf16_kernel(const float* __restrict__ in,
                                      bf16* __restrict__ out,
                                      int K, int N)
{
    __shared__ float tile[32][33];
    int x = blockIdx.x * 32 + threadIdx.x;
    int y0 = blockIdx.y * 32;
    #pragma unroll
    for (int j = 0; j < 32; j += 8) {
        int y = y0 + threadIdx.y + j;
        if (y < K && x < N)
            tile[threadIdx.y + j][threadIdx.x] = in[(size_t)y * N + x];
    }
    __syncthreads();
    int ox = y0 + threadIdx.x;
    int oy0 = blockIdx.x * 32;
    #pragma unroll
    for (int j = 0; j < 32; j += 8) {
        int oy = oy0 + threadIdx.y + j;
        if (oy < N && ox < K)
            out[(size_t)oy * K + ox] =
                __float2bfloat16_rn(tile[threadIdx.x][threadIdx.y + j]);
    }
}

// ---------------------------------------------------------------------------
// Mask dtype detection + normalization (proven since R2)
// ---------------------------------------------------------------------------
__global__ void detect_mask_kernel(const long long* __restrict__ m64)
{
    int i = blockIdx.x * blockDim.x + threadIdx.x;
    if (i < NMASK / 2) {
        unsigned long long v = (unsigned long long)m64[i];
        if (v > 1ULL) atomicOr(&g_mask_is32, 1);
    }
}
__global__ void normalize_mask_kernel(const void* __restrict__ mraw)
{
    int i = blockIdx.x * blockDim.x + threadIdx.x;
    if (i >= NMASK) return;
    float v;
    if (g_mask_is32) v = (float)((const int*)mraw)[i];
    else             v = (float)((const long long*)mraw)[i];
    g_maskf[i] = v;
}

// ---------------------------------------------------------------------------
// BF16 tensor-core GEMM (proven R6): C[M,N] = op(A[M,K] @ Bt[N,K]^T + bias)
// BM=128, BN=128, BK=64, 128 threads = 4 warps (2x2), warp tile 64x64.
// ---------------------------------------------------------------------------
#define BKQ 64
#define TSTRIDE 72
#define TILE_BF (128 * TSTRIDE)
#define SMEM_BYTES (4 * TILE_BF * 2)     // 73728 B

__device__ __forceinline__ void cp_async16(uint32_t dst, const void* src, int ssize)
{
    asm volatile("cp.async.cg.shared.global [%0], [%1], 16, %2;\n"
                 :: "r"(dst), "l"(src), "r"(ssize));
}
__device__ __forceinline__ void cp_commit() { asm volatile("cp.async.commit_group;\n"); }
__device__ __forceinline__ void cp_wait0()  { asm volatile("cp.async.wait_group 0;\n"); }

template <bool TANH, bool BIAS, bool OUT_BF16>
__global__ __launch_bounds__(128, 2)
void bf16_gemm(const bf16* __restrict__ A,
               const bf16* __restrict__ Bt,   // [N][K]
               const float* __restrict__ bias,
               void* __restrict__ Cv,
               int M, int N, int K)
{
    extern __shared__ bf16 smem[];
    bf16* As[2] = { smem,                smem + TILE_BF };
    bf16* Bs[2] = { smem + 2 * TILE_BF,  smem + 3 * TILE_BF };

    const int tid  = threadIdx.x;
    const int lane = tid & 31;
    const int wid  = tid >> 5;
    const int wm   = (wid & 1) * 64;
    const int wn   = (wid >> 1) * 64;
    const int g    = lane >> 2;
    const int tg   = lane & 3;
    const int m0   = blockIdx.y * 128;
    const int n0   = blockIdx.x * 128;

    const int crow = tid >> 3;
    const int ac   = (tid & 7) * 8;

    uint32_t as_base[2], bs_base[2];
    as_base[0] = (uint32_t)__cvta_generic_to_shared(As[0]);
    as_base[1] = (uint32_t)__cvta_generic_to_shared(As[1]);
    bs_base[0] = (uint32_t)__cvta_generic_to_shared(Bs[0]);
    bs_base[1] = (uint32_t)__cvta_generic_to_shared(Bs[1]);

    float acc[4][8][4];
    #pragma unroll
    for (int mi = 0; mi < 4; mi++)
        #pragma unroll
        for (int ni = 0; ni < 8; ni++)
            #pragma unroll
            for (int r = 0; r < 4; r++)
                acc[mi][ni][r] = 0.f;

    const int tiles = (K + BKQ - 1) / BKQ;

    auto load_tile = [&](int buf, int k0) {
        int gk = k0 + ac;
        int ok = (gk < K) ? 16 : 0;
        int gks = ok ? gk : 0;
        #pragma unroll
        for (int i = 0; i < 8; i++) {
            int row = crow + 16 * i;
            cp_async16(as_base[buf] + (row * TSTRIDE + ac) * 2,
                       A + (size_t)(m0 + row) * K + gks, ok);
        }
        #pragma unroll
        for (int i = 0; i < 8; i++) {
            int row = crow + 16 * i;
            cp_async16(bs_base[buf] + (row * TSTRIDE + ac) * 2,
                       Bt + (size_t)(n0 + row) * K + gks, ok);
        }
        cp_commit();
    };

    load_tile(0, 0);

    int buf = 0;
    for (int t = 0; t < tiles; t++) {
        cp_wait0();
        __syncthreads();
        if (t + 1 < tiles)
            load_tile(buf ^ 1, (t + 1) * BKQ);

        const bf16* Ab = As[buf];
        const bf16* Bb = Bs[buf];

        #pragma unroll
        for (int s = 0; s < BKQ / 16; s++) {
            const int kb = s * 16;
            uint32_t af[4][4];
            #pragma unroll
            for (int mi = 0; mi < 4; mi++) {
                const bf16* p = Ab + (wm + mi * 16 + g) * TSTRIDE + kb + 2 * tg;
                af[mi][0] = *reinterpret_cast<const uint32_t*>(p);
                af[mi][1] = *reinterpret_cast<const uint32_t*>(p + 8 * TSTRIDE);
                af[mi][2] = *reinterpret_cast<const uint32_t*>(p + 8);
                af[mi][3] = *reinterpret_cast<const uint32_t*>(p + 8 * TSTRIDE + 8);
            }
            uint32_t bfr[8][2];
            #pragma unroll
            for (int ni = 0; ni < 8; ni++) {
                const bf16* p = Bb + (wn + ni * 8 + g) * TSTRIDE + kb + 2 * tg;
                bfr[ni][0] = *reinterpret_cast<const uint32_t*>(p);
                bfr[ni][1] = *reinterpret_cast<const uint32_t*>(p + 8);
            }
            #pragma unroll
            for (int mi = 0; mi < 4; mi++)
                #pragma unroll
                for (int ni = 0; ni < 8; ni++) {
                    asm volatile(
                        "mma.sync.aligned.m16n8k16.row.col.f32.bf16.bf16.f32 "
                        "{%0,%1,%2,%3}, {%4,%5,%6,%7}, {%8,%9}, {%0,%1,%2,%3};\n"
                        : "+f"(acc[mi][ni][0]), "+f"(acc[mi][ni][1]),
                          "+f"(acc[mi][ni][2]), "+f"(acc[mi][ni][3])
                        : "r"(af[mi][0]), "r"(af[mi][1]), "r"(af[mi][2]), "r"(af[mi][3]),
                          "r"(bfr[ni][0]), "r"(bfr[ni][1]));
                }
        }
        buf ^= 1;
    }

    #pragma unroll
    for (int ni = 0; ni < 8; ni++) {
        const int col = n0 + wn + ni * 8 + tg * 2;
        float b0 = 0.f, b1 = 0.f;
        if (BIAS) { b0 = bias[col]; b1 = bias[col + 1]; }
        #pragma unroll
        for (int mi = 0; mi < 4; mi++) {
            const int row = m0 + wm + mi * 16 + g;
            float r0 = acc[mi][ni][0] + b0;
            float r1 = acc[mi][ni][1] + b1;
            float r2 = acc[mi][ni][2] + b0;
            float r3 = acc[mi][ni][3] + b1;
            if (TANH) { r0 = tanhf(r0); r1 = tanhf(r1); r2 = tanhf(r2); r3 = tanhf(r3); }
            if (OUT_BF16) {
                bf16* C = (bf16*)Cv;
                *reinterpret_cast<__nv_bfloat162*>(&C[(size_t)row * N + col]) =
                    __floats2bfloat162_rn(r0, r1);
                *reinterpret_cast<__nv_bfloat162*>(&C[(size_t)(row + 8) * N + col]) =
                    __floats2bfloat162_rn(r2, r3);
            } else {
                float* C = (float*)Cv;
                *reinterpret_cast<float2*>(&C[(size_t)row * N + col])       = make_float2(r0, r1);
                *reinterpret_cast<float2*>(&C[(size_t)(row + 8) * N + col]) = make_float2(r2, r3);
            }
        }
    }
}

// ---------------------------------------------------------------------------
// Attention kernel: per token bs:
//   score_w = <r_bs, tmp_{bs,w}>;  masked softmax over W=5;
//   ctx_bs = sum_w alpha_w * tmp_{bs,w}  -> bf16
// ---------------------------------------------------------------------------
__global__ __launch_bounds__(256)
void attn_kernel(bf16* __restrict__ ctxB)
{
    const int bs  = blockIdx.x;
    const int tid = threadIdx.x;

    __shared__ float red[5][256];
    __shared__ float s_alpha[5];

    const float* rrow  = g_r    + (size_t)bs * H_SZ;
    const bf16*  trow  = g_tmpB + (size_t)bs * W_SZ * H_SZ;

    float rv[3], tv[5][3];
    #pragma unroll
    for (int e = 0; e < 3; e++) {
        int h = tid + e * 256;
        rv[e] = rrow[h];
        #pragma unroll
        for (int w = 0; w < W_SZ; w++)
            tv[w][e] = __bfloat162float(trow[w * H_SZ + h]);
    }

    #pragma unroll
    for (int w = 0; w < W_SZ; w++) {
        float d = 0.f;
        #pragma unroll
        for (int e = 0; e < 3; e++)
            d = fmaf(rv[e], tv[w][e], d);
        red[w][tid] = d;
    }
    __syncthreads();
    for (int s = 128; s > 0; s >>= 1) {
        if (tid < s) {
            #pragma unroll
            for (int w = 0; w < W_SZ; w++)
                red[w][tid] += red[w][tid + s];
        }
        __syncthreads();
    }

    if (tid == 0) {
        float sc[5];
        float mx = -1e30f;
        #pragma unroll
        for (int w = 0; w < W_SZ; w++) {
            float mk = g_maskf[(size_t)bs * W_SZ + w];
            sc[w] = red[w][0] + (1.f - mk) * (-10000.f);
            mx = fmaxf(mx, sc[w]);
        }
        float sum = 0.f;
        #pragma unroll
        for (int w = 0; w < W_SZ; w++) {
            sc[w] = expf(sc[w] - mx);
            sum += sc[w];
        }
        float inv = 1.f / sum;
        #pragma unroll
        for (int w = 0; w < W_SZ; w++)
            s_alpha[w] = sc[w] * inv;
    }
    __syncthreads();

    float alpha[5];
    #pragma unroll
    for (int w = 0; w < W_SZ; w++) alpha[w] = s_alpha[w];

    #pragma unroll
    for (int e = 0; e < 3; e++) {
        int h = tid + e * 256;
        float c = 0.f;
        #pragma unroll
        for (int w = 0; w < W_SZ; w++)
            c = fmaf(alpha[w], tv[w][e], c);
        ctxB[(size_t)bs * H_SZ + h] = __float2bfloat16_rn(c);
    }
}

// ---------------------------------------------------------------------------
// Residual + LayerNorm: out = LN(lo + agg) * gamma + beta
// ---------------------------------------------------------------------------
__global__ __launch_bounds__(256)
void ln_kernel(const float* __restrict__ lo,
               const float* __restrict__ gamma,
               const float* __restrict__ beta,
               float* __restrict__ out)
{
    const int bs  = blockIdx.x;
    const int tid = threadIdx.x;

    __shared__ float red0[256], red1[256];

    const float* lorow = lo    + (size_t)bs * H_SZ;
    const float* agrow = g_agg + (size_t)bs * H_SZ;

    float hv[3];
    float psum = 0.f, psq = 0.f;
    #pragma unroll
    for (int e = 0; e < 3; e++) {
        int h = tid + e * 256;
        hv[e] = lorow[h] + agrow[h];
        psum += hv[e];
        psq  = fmaf(hv[e], hv[e], psq);
    }
    red0[tid] = psum;
    red1[tid] = psq;
    __syncthreads();
    for (int s = 128; s > 0; s >>= 1) {
        if (tid < s) {
            red0[tid] += red0[tid + s];
            red1[tid] += red1[tid + s];
        }
        __syncthreads();
    }

    const float inv_h = 1.f / (float)H_SZ;
    float mu   = red0[0] * inv_h;
    float var  = red1[0] * inv_h - mu * mu;
    float rstd = rsqrtf(var + 1e-12f);

    #pragma unroll
    for (int e = 0; e < 3; e++) {
        int h = tid + e * 256;
        out[(size_t)bs * H_SZ + h] = (hv[e] - mu) * rstd * gamma[h] + beta[h];
    }
}

// ---------------------------------------------------------------------------
// Launch
// ---------------------------------------------------------------------------
extern "C" void kernel_launch(void* const* d_in, const int* in_sizes, int n_in,
                              void* d_out, int out_size)
{
    const float* lo     = (const float*)d_in[0];
    const float* we_in  = (const float*)d_in[1];
    const void*  mask   = d_in[2];
    const float* W1     = (const float*)d_in[3];
    const float* b1     = (const float*)d_in[4];
    const float* W2     = (const float*)d_in[5];
    const float* b2     = (const float*)d_in[6];
    const float* attn_W = (const float*)d_in[7];
    const float* gamma  = (const float*)d_in[8];
    const float* beta   = (const float*)d_in[9];
    float*       out    = (float*)d_out;

    bf16 *weB_p, *loB_p, *tmpB_p, *ctxB_p, *w1t_p, *w2b_p, *w2t_p, *awb_p, *wct_p;
    float *r_p, *agg_p;
    cudaGetSymbolAddress((void**)&weB_p,  g_weB);
    cudaGetSymbolAddress((void**)&loB_p,  g_loB);
    cudaGetSymbolAddress((void**)&tmpB_p, g_tmpB);
    cudaGetSymbolAddress((void**)&ctxB_p, g_ctxB);
    cudaGetSymbolAddress((void**)&w1t_p,  g_W1T);
    cudaGetSymbolAddress((void**)&w2b_p,  g_W2B);
    cudaGetSymbolAddress((void**)&w2t_p,  g_W2T);
    cudaGetSymbolAddress((void**)&awb_p,  g_aWB);
    cudaGetSymbolAddress((void**)&wct_p,  g_WcT);
    cudaGetSymbolAddress((void**)&r_p,    g_r);
    cudaGetSymbolAddress((void**)&agg_p,  g_agg);

    cudaFuncSetAttribute(bf16_gemm<true,  true,  true >, cudaFuncAttributeMaxDynamicSharedMemorySize, SMEM_BYTES);
    cudaFuncSetAttribute(bf16_gemm<false, false, true >, cudaFuncAttributeMaxDynamicSharedMemorySize, SMEM_BYTES);
    cudaFuncSetAttribute(bf16_gemm<false, false, false>, cudaFuncAttributeMaxDynamicSharedMemorySize, SMEM_BYTES);
    cudaFuncSetAttribute(bf16_gemm<false, true,  false>, cudaFuncAttributeMaxDynamicSharedMemorySize, SMEM_BYTES);

    // Mask handling
    int* flag_p;
    cudaGetSymbolAddress((void**)&flag_p, g_mask_is32);
    cudaMemsetAsync(flag_p, 0, sizeof(int));
    detect_mask_kernel<<<(NMASK / 2 + 255) / 256, 256>>>((const long long*)mask);
    normalize_mask_kernel<<<(NMASK + 255) / 256, 256>>>(mask);

    // Pre-convert to bf16 (activations + plain weight copies)
    f32_to_bf16_kernel<<<(M1 * D_SZ / 4 + 255) / 256, 256>>>(we_in,  weB_p, M1 * D_SZ);
    f32_to_bf16_kernel<<<(MQ * H_SZ / 4 + 255) / 256, 256>>>(lo,     loB_p, MQ * H_SZ);
    f32_to_bf16_kernel<<<(H_SZ * H_SZ / 4 + 255) / 256, 256>>>(W2,    w2b_p, H_SZ * H_SZ);
    f32_to_bf16_kernel<<<(H_SZ * H_SZ / 4 + 255) / 256, 256>>>(attn_W, awb_p, H_SZ * H_SZ);

    // Transpose + convert weights: [K][N] fp32 -> [N][K] bf16
    {
        dim3 tb(32, 8);
        dim3 g1((H_SZ + 31) / 32, (D_SZ + 31) / 32);
        dim3 g2((H_SZ + 31) / 32, (H_SZ + 31) / 32);
        transpose_bf16_kernel<<<g1, tb>>>(W1, w1t_p, D_SZ, H_SZ);
        transpose_bf16_kernel<<<g2, tb>>>(W2, w2t_p, H_SZ, H_SZ);
    }

    dim3 blk(128);
    dim3 grid1(H_SZ / 128, M1 / 128);   // (6, 320)
    dim3 gridQ(H_SZ / 128, MQ / 128);   // (6, 64)
    dim3 gridW(H_SZ / 128, H_SZ / 128); // (6, 6)

    // Wc GEMM: WcT[n][k] = sum_h W2[n][h] * attn_W[k][h]   [768 x 768], K=768
    bf16_gemm<false, false, true ><<<gridW, blk, SMEM_BYTES>>>(w2b_p, awb_p, nullptr, wct_p, H_SZ, H_SZ, H_SZ);
    // GEMM1: tmpB = bf16(tanh(WE @ W1 + b1))               [40960 x 768], K=200
    bf16_gemm<true,  true,  true ><<<grid1, blk, SMEM_BYTES>>>(weB_p, w1t_p, b1, tmpB_p, M1, H_SZ, D_SZ);
    // GEMM_r: r = loB @ Wc  (Bt = WcT)                     [8192 x 768], K=768, fp32 out
    bf16_gemm<false, false, false><<<gridQ, blk, SMEM_BYTES>>>(loB_p, wct_p, nullptr, r_p, MQ, H_SZ, H_SZ);
    // Attention: scores via <r, tmp_w>, softmax, ctx = sum alpha_w tmp_w (bf16)
    attn_kernel<<<MQ, 256>>>(ctxB_p);
    // GEMM_agg: agg = ctx @ W2 + b2  (Bt = W2T)            [8192 x 768], K=768, fp32 out
    bf16_gemm<false, true,  false><<<gridQ, blk, SMEM_BYTES>>>(ctxB_p, w2t_p, b2, agg_p, MQ, H_SZ, H_SZ);
    // Residual + LayerNorm
    ln_kernel<<<MQ, 256>>>(lo, gamma, beta, out);
}

// round 10
// speedup vs baseline: 2.3848x; 1.0564x over previous
#include <cuda_runtime.h>
#include <cuda_bf16.h>
#include <math.h>
#include <stdint.h>

typedef __nv_bfloat16 bf16;

// Problem dimensions (fixed by the reference)
#define B_SZ 16
#define S_SZ 512
#define W_SZ 5
#define D_SZ 200
#define H_SZ 768
#define M1 (B_SZ * S_SZ * W_SZ)   // 40960
#define MQ (B_SZ * S_SZ)          // 8192
#define NMASK (MQ * W_SZ)         // 40960
#define MB1 (M1 / 128)            // 320 m-blocks for GEMM1
#define MBQ (MQ / 128)            // 64 m-blocks for token GEMMs

// Scratch (alloc-free rule: __device__ globals)
__device__ __align__(16) bf16 g_weB [M1 * D_SZ];
__device__ __align__(16) bf16 g_loB [MQ * H_SZ];
__device__ __align__(16) bf16 g_tmpB[M1 * H_SZ];
__device__ __align__(16) bf16 g_ctxB[MQ * H_SZ];
__device__ __align__(16) bf16 g_W1T [H_SZ * D_SZ];
__device__ __align__(16) bf16 g_W2B [H_SZ * H_SZ];
__device__ __align__(16) bf16 g_W2T [H_SZ * H_SZ];
__device__ __align__(16) bf16 g_aWB [H_SZ * H_SZ];
__device__ __align__(16) bf16 g_WcT [H_SZ * H_SZ];
__device__ float g_r  [MQ * H_SZ];
__device__ float g_agg[MQ * H_SZ];
__device__ float g_maskf[NMASK];
__device__ int   g_mask_is32;

// ---------------------------------------------------------------------------
// One segmented fp32->bf16 convert for all 4 buffers (1 launch)
// ---------------------------------------------------------------------------
#define CN0 (M1 * D_SZ)       // we_in
#define CN1 (MQ * H_SZ)       // lo
#define CN2 (H_SZ * H_SZ)     // W2
#define CN3 (H_SZ * H_SZ)     // attn_W
#define CNT (CN0 + CN1 + CN2 + CN3)

__global__ void conv_all_kernel(const float* __restrict__ p0,
                                const float* __restrict__ p1,
                                const float* __restrict__ p2,
                                const float* __restrict__ p3)
{
    long idx = ((long)blockIdx.x * blockDim.x + threadIdx.x) * 4;
    if (idx >= CNT) return;
    const float* in;
    bf16* out;
    long off;
    if (idx < CN0)                    { in = p0; out = g_weB; off = idx; }
    else if (idx < CN0 + CN1)         { in = p1; out = g_loB; off = idx - CN0; }
    else if (idx < CN0 + CN1 + CN2)   { in = p2; out = g_W2B; off = idx - CN0 - CN1; }
    else                              { in = p3; out = g_aWB; off = idx - CN0 - CN1 - CN2; }
    float4 v = *reinterpret_cast<const float4*>(in + off);
    *reinterpret_cast<__nv_bfloat162*>(out + off)     = __floats2bfloat162_rn(v.x, v.y);
    *reinterpret_cast<__nv_bfloat162*>(out + off + 2) = __floats2bfloat162_rn(v.z, v.w);
}

// ---------------------------------------------------------------------------
// One transpose+convert launch for W1 and W2 (z selects)
// ---------------------------------------------------------------------------
__global__ void trans_all_kernel(const float* __restrict__ W1,
                                 const float* __restrict__ W2)
{
    const int z = blockIdx.z;
    const float* in = z ? W2 : W1;
    bf16* out = z ? g_W2T : g_W1T;
    const int K = z ? H_SZ : D_SZ;
    const int N = H_SZ;
    if (blockIdx.y * 32 >= K) return;

    __shared__ float tile[32][33];
    int x = blockIdx.x * 32 + threadIdx.x;
    int y0 = blockIdx.y * 32;
    #pragma unroll
    for (int j = 0; j < 32; j += 8) {
        int y = y0 + threadIdx.y + j;
        if (y < K && x < N)
            tile[threadIdx.y + j][threadIdx.x] = in[(size_t)y * N + x];
    }
    __syncthreads();
    int ox = y0 + threadIdx.x;
    int oy0 = blockIdx.x * 32;
    #pragma unroll
    for (int j = 0; j < 32; j += 8) {
        int oy = oy0 + threadIdx.y + j;
        if (oy < N && ox < K)
            out[(size_t)oy * K + ox] =
                __float2bfloat16_rn(tile[threadIdx.x][threadIdx.y + j]);
    }
}

// ---------------------------------------------------------------------------
// Mask dtype detection + normalization (proven since R2)
// ---------------------------------------------------------------------------
__global__ void detect_mask_kernel(const long long* __restrict__ m64)
{
    int i = blockIdx.x * blockDim.x + threadIdx.x;
    if (i < NMASK / 2) {
        unsigned long long v = (unsigned long long)m64[i];
        if (v > 1ULL) atomicOr(&g_mask_is32, 1);
    }
}
__global__ void normalize_mask_kernel(const void* __restrict__ mraw)
{
    int i = blockIdx.x * blockDim.x + threadIdx.x;
    if (i >= NMASK) return;
    float v;
    if (g_mask_is32) v = (float)((const int*)mraw)[i];
    else             v = (float)((const long long*)mraw)[i];
    g_maskf[i] = v;
}

// ---------------------------------------------------------------------------
// Shared GEMM machinery
// ---------------------------------------------------------------------------
#define BKQ 64
#define TSTRIDE 72
#define TILE_BF (128 * TSTRIDE)
#define SMEM_BYTES (4 * TILE_BF * 2)     // 73728 B

__device__ __forceinline__ void cp_async16(uint32_t dst, const void* src, int ssize)
{
    asm volatile("cp.async.cg.shared.global [%0], [%1], 16, %2;\n"
                 :: "r"(dst), "l"(src), "r"(ssize));
}
__device__ __forceinline__ void cp_commit() { asm volatile("cp.async.commit_group;\n"); }
__device__ __forceinline__ void cp_wait0()  { asm volatile("cp.async.wait_group 0;\n"); }

#define MMA_BF16(acc, af, bf0, bf1)                                            \
    asm volatile(                                                              \
        "mma.sync.aligned.m16n8k16.row.col.f32.bf16.bf16.f32 "                 \
        "{%0,%1,%2,%3}, {%4,%5,%6,%7}, {%8,%9}, {%0,%1,%2,%3};\n"              \
        : "+f"((acc)[0]), "+f"((acc)[1]), "+f"((acc)[2]), "+f"((acc)[3])       \
        : "r"((af)[0]), "r"((af)[1]), "r"((af)[2]), "r"((af)[3]),              \
          "r"(bf0), "r"(bf1))

// ---------------------------------------------------------------------------
// Template bf16 GEMM (proven R6) — used for Wc and GEMM_agg (K % 64 == 0)
// ---------------------------------------------------------------------------
template <bool TANH, bool BIAS, bool OUT_BF16>
__global__ __launch_bounds__(128, 2)
void bf16_gemm(const bf16* __restrict__ A,
               const bf16* __restrict__ Bt,
               const float* __restrict__ bias,
               void* __restrict__ Cv,
               int M, int N, int K)
{
    extern __shared__ bf16 smem[];
    bf16* As[2] = { smem,                smem + TILE_BF };
    bf16* Bs[2] = { smem + 2 * TILE_BF,  smem + 3 * TILE_BF };

    const int tid  = threadIdx.x;
    const int lane = tid & 31;
    const int wid  = tid >> 5;
    const int wm   = (wid & 1) * 64;
    const int wn   = (wid >> 1) * 64;
    const int g    = lane >> 2;
    const int tg   = lane & 3;
    const int m0   = blockIdx.y * 128;
    const int n0   = blockIdx.x * 128;

    const int crow = tid >> 3;
    const int ac   = (tid & 7) * 8;

    uint32_t as_base[2], bs_base[2];
    as_base[0] = (uint32_t)__cvta_generic_to_shared(As[0]);
    as_base[1] = (uint32_t)__cvta_generic_to_shared(As[1]);
    bs_base[0] = (uint32_t)__cvta_generic_to_shared(Bs[0]);
    bs_base[1] = (uint32_t)__cvta_generic_to_shared(Bs[1]);

    float acc[4][8][4];
    #pragma unroll
    for (int mi = 0; mi < 4; mi++)
        #pragma unroll
        for (int ni = 0; ni < 8; ni++)
            #pragma unroll
            for (int r = 0; r < 4; r++)
                acc[mi][ni][r] = 0.f;

    const int tiles = (K + BKQ - 1) / BKQ;

    auto load_tile = [&](int buf, int k0) {
        int gk = k0 + ac;
        int ok = (gk < K) ? 16 : 0;
        int gks = ok ? gk : 0;
        #pragma unroll
        for (int i = 0; i < 8; i++) {
            int row = crow + 16 * i;
            cp_async16(as_base[buf] + (row * TSTRIDE + ac) * 2,
                       A + (size_t)(m0 + row) * K + gks, ok);
        }
        #pragma unroll
        for (int i = 0; i < 8; i++) {
            int row = crow + 16 * i;
            cp_async16(bs_base[buf] + (row * TSTRIDE + ac) * 2,
                       Bt + (size_t)(n0 + row) * K + gks, ok);
        }
        cp_commit();
    };

    load_tile(0, 0);

    int buf = 0;
    for (int t = 0; t < tiles; t++) {
        cp_wait0();
        __syncthreads();
        if (t + 1 < tiles)
            load_tile(buf ^ 1, (t + 1) * BKQ);

        const bf16* Ab = As[buf];
        const bf16* Bb = Bs[buf];

        #pragma unroll
        for (int s = 0; s < BKQ / 16; s++) {
            const int kb = s * 16;
            uint32_t af[4][4];
            #pragma unroll
            for (int mi = 0; mi < 4; mi++) {
                const bf16* p = Ab + (wm + mi * 16 + g) * TSTRIDE + kb + 2 * tg;
                af[mi][0] = *reinterpret_cast<const uint32_t*>(p);
                af[mi][1] = *reinterpret_cast<const uint32_t*>(p + 8 * TSTRIDE);
                af[mi][2] = *reinterpret_cast<const uint32_t*>(p + 8);
                af[mi][3] = *reinterpret_cast<const uint32_t*>(p + 8 * TSTRIDE + 8);
            }
            uint32_t bfr[8][2];
            #pragma unroll
            for (int ni = 0; ni < 8; ni++) {
                const bf16* p = Bb + (wn + ni * 8 + g) * TSTRIDE + kb + 2 * tg;
                bfr[ni][0] = *reinterpret_cast<const uint32_t*>(p);
                bfr[ni][1] = *reinterpret_cast<const uint32_t*>(p + 8);
            }
            #pragma unroll
            for (int mi = 0; mi < 4; mi++)
                #pragma unroll
                for (int ni = 0; ni < 8; ni++)
                    MMA_BF16(acc[mi][ni], af[mi], bfr[ni][0], bfr[ni][1]);
        }
        buf ^= 1;
    }

    #pragma unroll
    for (int ni = 0; ni < 8; ni++) {
        const int col = n0 + wn + ni * 8 + tg * 2;
        float b0 = 0.f, b1 = 0.f;
        if (BIAS) { b0 = bias[col]; b1 = bias[col + 1]; }
        #pragma unroll
        for (int mi = 0; mi < 4; mi++) {
            const int row = m0 + wm + mi * 16 + g;
            float r0 = acc[mi][ni][0] + b0;
            float r1 = acc[mi][ni][1] + b1;
            float r2 = acc[mi][ni][2] + b0;
            float r3 = acc[mi][ni][3] + b1;
            if (TANH) { r0 = tanhf(r0); r1 = tanhf(r1); r2 = tanhf(r2); r3 = tanhf(r3); }
            if (OUT_BF16) {
                bf16* C = (bf16*)Cv;
                *reinterpret_cast<__nv_bfloat162*>(&C[(size_t)row * N + col]) =
                    __floats2bfloat162_rn(r0, r1);
                *reinterpret_cast<__nv_bfloat162*>(&C[(size_t)(row + 8) * N + col]) =
                    __floats2bfloat162_rn(r2, r3);
            } else {
                float* C = (float*)Cv;
                *reinterpret_cast<float2*>(&C[(size_t)row * N + col])       = make_float2(r0, r1);
                *reinterpret_cast<float2*>(&C[(size_t)(row + 8) * N + col]) = make_float2(r2, r3);
            }
        }
    }
}

// ---------------------------------------------------------------------------
// Merged GEMM1 + GEMM_r kernel. grid (6, MB1 + MBQ).
//   y <  MB1: tmpB = bf16(tanh(weB @ W1T^T + b1)), K=200 (ragged: 13 k16 steps)
//   y >= MB1: r    = loB @ WcT^T (fp32 out),        K=768
// ---------------------------------------------------------------------------
__global__ __launch_bounds__(128, 2)
void gemm_main(const float* __restrict__ b1)
{
    extern __shared__ bf16 smem[];
    bf16* As[2] = { smem,                smem + TILE_BF };
    bf16* Bs[2] = { smem + 2 * TILE_BF,  smem + 3 * TILE_BF };

    const int tid  = threadIdx.x;
    const int lane = tid & 31;
    const int wid  = tid >> 5;
    const int wm   = (wid & 1) * 64;
    const int wn   = (wid >> 1) * 64;
    const int g    = lane >> 2;
    const int tg   = lane & 3;
    const int n0   = blockIdx.x * 128;

    const bool first = (blockIdx.y < MB1);
    const bf16* A  = first ? g_weB : g_loB;
    const bf16* Bt = first ? g_W1T : g_WcT;
    const int   K  = first ? D_SZ  : H_SZ;
    const int   m0 = (first ? blockIdx.y : (blockIdx.y - MB1)) * 128;

    const int crow = tid >> 3;
    const int ac   = (tid & 7) * 8;

    uint32_t as_base[2], bs_base[2];
    as_base[0] = (uint32_t)__cvta_generic_to_shared(As[0]);
    as_base[1] = (uint32_t)__cvta_generic_to_shared(As[1]);
    bs_base[0] = (uint32_t)__cvta_generic_to_shared(Bs[0]);
    bs_base[1] = (uint32_t)__cvta_generic_to_shared(Bs[1]);

    float acc[4][8][4];
    #pragma unroll
    for (int mi = 0; mi < 4; mi++)
        #pragma unroll
        for (int ni = 0; ni < 8; ni++)
            #pragma unroll
            for (int r = 0; r < 4; r++)
                acc[mi][ni][r] = 0.f;

    const int kt16  = (K + 15) >> 4;        // 13 or 48
    const int tiles = (kt16 + 3) >> 2;      // 4 or 12

    auto load_tile = [&](int buf, int k0) {
        int gk = k0 + ac;
        int ok = (gk < K) ? 16 : 0;
        int gks = ok ? gk : 0;
        #pragma unroll
        for (int i = 0; i < 8; i++) {
            int row = crow + 16 * i;
            cp_async16(as_base[buf] + (row * TSTRIDE + ac) * 2,
                       A + (size_t)(m0 + row) * K + gks, ok);
        }
        #pragma unroll
        for (int i = 0; i < 8; i++) {
            int row = crow + 16 * i;
            cp_async16(bs_base[buf] + (row * TSTRIDE + ac) * 2,
                       Bt + (size_t)(n0 + row) * K + gks, ok);
        }
        cp_commit();
    };

    load_tile(0, 0);

    int buf = 0;
    for (int t = 0; t < tiles; t++) {
        cp_wait0();
        __syncthreads();
        if (t + 1 < tiles)
            load_tile(buf ^ 1, (t + 1) * BKQ);

        const bf16* Ab = As[buf];
        const bf16* Bb = Bs[buf];
        const int slim = kt16 - (t << 2);   // >= 1; 4 except last ragged tile

        #pragma unroll
        for (int s = 0; s < 4; s++) {
            if (s >= slim) break;
            const int kb = s * 16;
            uint32_t af[4][4];
            #pragma unroll
            for (int mi = 0; mi < 4; mi++) {
                const bf16* p = Ab + (wm + mi * 16 + g) * TSTRIDE + kb + 2 * tg;
                af[mi][0] = *reinterpret_cast<const uint32_t*>(p);
                af[mi][1] = *reinterpret_cast<const uint32_t*>(p + 8 * TSTRIDE);
                af[mi][2] = *reinterpret_cast<const uint32_t*>(p + 8);
                af[mi][3] = *reinterpret_cast<const uint32_t*>(p + 8 * TSTRIDE + 8);
            }
            uint32_t bfr[8][2];
            #pragma unroll
            for (int ni = 0; ni < 8; ni++) {
                const bf16* p = Bb + (wn + ni * 8 + g) * TSTRIDE + kb + 2 * tg;
                bfr[ni][0] = *reinterpret_cast<const uint32_t*>(p);
                bfr[ni][1] = *reinterpret_cast<const uint32_t*>(p + 8);
            }
            #pragma unroll
            for (int mi = 0; mi < 4; mi++)
                #pragma unroll
                for (int ni = 0; ni < 8; ni++)
                    MMA_BF16(acc[mi][ni], af[mi], bfr[ni][0], bfr[ni][1]);
        }
        buf ^= 1;
    }

    if (first) {
        #pragma unroll
        for (int ni = 0; ni < 8; ni++) {
            const int col = n0 + wn + ni * 8 + tg * 2;
            const float b0 = b1[col];
            const float bb1 = b1[col + 1];
            #pragma unroll
            for (int mi = 0; mi < 4; mi++) {
                const int row = m0 + wm + mi * 16 + g;
                float r0 = tanhf(acc[mi][ni][0] + b0);
                float r1 = tanhf(acc[mi][ni][1] + bb1);
                float r2 = tanhf(acc[mi][ni][2] + b0);
                float r3 = tanhf(acc[mi][ni][3] + bb1);
                *reinterpret_cast<__nv_bfloat162*>(&g_tmpB[(size_t)row * H_SZ + col]) =
                    __floats2bfloat162_rn(r0, r1);
                *reinterpret_cast<__nv_bfloat162*>(&g_tmpB[(size_t)(row + 8) * H_SZ + col]) =
                    __floats2bfloat162_rn(r2, r3);
            }
        }
    } else {
        #pragma unroll
        for (int ni = 0; ni < 8; ni++) {
            const int col = n0 + wn + ni * 8 + tg * 2;
            #pragma unroll
            for (int mi = 0; mi < 4; mi++) {
                const int row = m0 + wm + mi * 16 + g;
                *reinterpret_cast<float2*>(&g_r[(size_t)row * H_SZ + col]) =
                    make_float2(acc[mi][ni][0], acc[mi][ni][1]);
                *reinterpret_cast<float2*>(&g_r[(size_t)(row + 8) * H_SZ + col]) =
                    make_float2(acc[mi][ni][2], acc[mi][ni][3]);
            }
        }
    }
}

// ---------------------------------------------------------------------------
// Attention kernel (proven R8/R9)
// ---------------------------------------------------------------------------
__global__ __launch_bounds__(256)
void attn_kernel(bf16* __restrict__ ctxB)
{
    const int bs  = blockIdx.x;
    const int tid = threadIdx.x;

    __shared__ float red[5][256];
    __shared__ float s_alpha[5];

    const float* rrow  = g_r    + (size_t)bs * H_SZ;
    const bf16*  trow  = g_tmpB + (size_t)bs * W_SZ * H_SZ;

    float rv[3], tv[5][3];
    #pragma unroll
    for (int e = 0; e < 3; e++) {
        int h = tid + e * 256;
        rv[e] = rrow[h];
        #pragma unroll
        for (int w = 0; w < W_SZ; w++)
            tv[w][e] = __bfloat162float(trow[w * H_SZ + h]);
    }

    #pragma unroll
    for (int w = 0; w < W_SZ; w++) {
        float d = 0.f;
        #pragma unroll
        for (int e = 0; e < 3; e++)
            d = fmaf(rv[e], tv[w][e], d);
        red[w][tid] = d;
    }
    __syncthreads();
    for (int s = 128; s > 0; s >>= 1) {
        if (tid < s) {
            #pragma unroll
            for (int w = 0; w < W_SZ; w++)
                red[w][tid] += red[w][tid + s];
        }
        __syncthreads();
    }

    if (tid == 0) {
        float sc[5];
        float mx = -1e30f;
        #pragma unroll
        for (int w = 0; w < W_SZ; w++) {
            float mk = g_maskf[(size_t)bs * W_SZ + w];
            sc[w] = red[w][0] + (1.f - mk) * (-10000.f);
            mx = fmaxf(mx, sc[w]);
        }
        float sum = 0.f;
        #pragma unroll
        for (int w = 0; w < W_SZ; w++) {
            sc[w] = expf(sc[w] - mx);
            sum += sc[w];
        }
        float inv = 1.f / sum;
        #pragma unroll
        for (int w = 0; w < W_SZ; w++)
            s_alpha[w] = sc[w] * inv;
    }
    __syncthreads();

    float alpha[5];
    #pragma unroll
    for (int w = 0; w < W_SZ; w++) alpha[w] = s_alpha[w];

    #pragma unroll
    for (int e = 0; e < 3; e++) {
        int h = tid + e * 256;
        float c = 0.f;
        #pragma unroll
        for (int w = 0; w < W_SZ; w++)
            c = fmaf(alpha[w], tv[w][e], c);
        ctxB[(size_t)bs * H_SZ + h] = __float2bfloat16_rn(c);
    }
}

// ---------------------------------------------------------------------------
// Residual + LayerNorm (proven R8/R9)
// ---------------------------------------------------------------------------
__global__ __launch_bounds__(256)
void ln_kernel(const float* __restrict__ lo,
               const float* __restrict__ gamma,
               const float* __restrict__ beta,
               float* __restrict__ out)
{
    const int bs  = blockIdx.x;
    const int tid = threadIdx.x;

    __shared__ float red0[256], red1[256];

    const float* lorow = lo    + (size_t)bs * H_SZ;
    const float* agrow = g_agg + (size_t)bs * H_SZ;

    float hv[3];
    float psum = 0.f, psq = 0.f;
    #pragma unroll
    for (int e = 0; e < 3; e++) {
        int h = tid + e * 256;
        hv[e] = lorow[h] + agrow[h];
        psum += hv[e];
        psq  = fmaf(hv[e], hv[e], psq);
    }
    red0[tid] = psum;
    red1[tid] = psq;
    __syncthreads();
    for (int s = 128; s > 0; s >>= 1) {
        if (tid < s) {
            red0[tid] += red0[tid + s];
            red1[tid] += red1[tid + s];
        }
        __syncthreads();
    }

    const float inv_h = 1.f / (float)H_SZ;
    float mu   = red0[0] * inv_h;
    float var  = red1[0] * inv_h - mu * mu;
    float rstd = rsqrtf(var + 1e-12f);

    #pragma unroll
    for (int e = 0; e < 3; e++) {
        int h = tid + e * 256;
        out[(size_t)bs * H_SZ + h] = (hv[e] - mu) * rstd * gamma[h] + beta[h];
    }
}

// ---------------------------------------------------------------------------
// Launch
// ---------------------------------------------------------------------------
extern "C" void kernel_launch(void* const* d_in, const int* in_sizes, int n_in,
                              void* d_out, int out_size)
{
    const float* lo     = (const float*)d_in[0];
    const float* we_in  = (const float*)d_in[1];
    const void*  mask   = d_in[2];
    const float* W1     = (const float*)d_in[3];
    const float* b1     = (const float*)d_in[4];
    const float* W2     = (const float*)d_in[5];
    const float* b2     = (const float*)d_in[6];
    const float* attn_W = (const float*)d_in[7];
    const float* gamma  = (const float*)d_in[8];
    const float* beta   = (const float*)d_in[9];
    float*       out    = (float*)d_out;

    bf16 *ctxB_p, *w2b_p, *w2t_p, *awb_p, *wct_p;
    float *agg_p;
    cudaGetSymbolAddress((void**)&ctxB_p, g_ctxB);
    cudaGetSymbolAddress((void**)&w2b_p,  g_W2B);
    cudaGetSymbolAddress((void**)&w2t_p,  g_W2T);
    cudaGetSymbolAddress((void**)&awb_p,  g_aWB);
    cudaGetSymbolAddress((void**)&wct_p,  g_WcT);
    cudaGetSymbolAddress((void**)&agg_p,  g_agg);

    cudaFuncSetAttribute(bf16_gemm<false, false, true >, cudaFuncAttributeMaxDynamicSharedMemorySize, SMEM_BYTES);
    cudaFuncSetAttribute(bf16_gemm<false, true,  false>, cudaFuncAttributeMaxDynamicSharedMemorySize, SMEM_BYTES);
    cudaFuncSetAttribute(gemm_main, cudaFuncAttributeMaxDynamicSharedMemorySize, SMEM_BYTES);

    // Mask handling
    int* flag_p;
    cudaGetSymbolAddress((void**)&flag_p, g_mask_is32);
    cudaMemsetAsync(flag_p, 0, sizeof(int));
    detect_mask_kernel<<<(NMASK / 2 + 255) / 256, 256>>>((const long long*)mask);
    normalize_mask_kernel<<<(NMASK + 255) / 256, 256>>>(mask);

    // All fp32->bf16 converts in one launch
    conv_all_kernel<<<(CNT / 4 + 255) / 256, 256>>>(we_in, lo, W2, attn_W);
    // Both weight transposes in one launch
    {
        dim3 tb(32, 8);
        dim3 tg(24, 24, 2);
        trans_all_kernel<<<tg, tb>>>(W1, W2);
    }

    dim3 blk(128);

    // Wc GEMM: WcT[n][k] = sum_h W2[n][h] * attn_W[k][h]   [768x768], K=768
    bf16_gemm<false, false, true ><<<dim3(6, 6), blk, SMEM_BYTES>>>(
        w2b_p, awb_p, nullptr, wct_p, H_SZ, H_SZ, H_SZ);
    // Merged GEMM1 (ragged K=200) + GEMM_r (K=768): one launch, 2304 CTAs
    gemm_main<<<dim3(6, MB1 + MBQ), blk, SMEM_BYTES>>>(b1);
    // Attention: scores via <r, tmp_w>, softmax, ctx (bf16)
    attn_kernel<<<MQ, 256>>>(ctxB_p);
    // GEMM_agg: agg = ctx @ W2 + b2   [8192x768], K=768, fp32 out
    bf16_gemm<false, true,  false><<<dim3(6, MBQ), blk, SMEM_BYTES>>>(
        ctxB_p, w2t_p, b2, agg_p, MQ, H_SZ, H_SZ);
    // Residual + LayerNorm
    ln_kernel<<<MQ, 256>>>(lo, gamma, beta, out);
}

// round 11
// speedup vs baseline: 2.6048x; 1.0923x over previous
#include <cuda_runtime.h>
#include <cuda_bf16.h>
#include <math.h>
#include <stdint.h>

typedef __nv_bfloat16 bf16;

// Problem dimensions (fixed by the reference)
#define B_SZ 16
#define S_SZ 512
#define W_SZ 5
#define D_SZ 200
#define H_SZ 768
#define M1 (B_SZ * S_SZ * W_SZ)   // 40960
#define MQ (B_SZ * S_SZ)          // 8192
#define NMASK (MQ * W_SZ)         // 40960
#define MB1 (M1 / 128)            // 320
#define MBQ (MQ / 128)            // 64
#define WC_SPLIT 6                // K-chunks for Wc split-K

// Scratch (alloc-free rule: __device__ globals)
__device__ __align__(16) bf16 g_weB [M1 * D_SZ];
__device__ __align__(16) bf16 g_loB [MQ * H_SZ];
__device__ __align__(16) bf16 g_tmpB[M1 * H_SZ];
__device__ __align__(16) bf16 g_ctxB[MQ * H_SZ];
__device__ __align__(16) bf16 g_W1T [H_SZ * D_SZ];
__device__ __align__(16) bf16 g_W2B [H_SZ * H_SZ];
__device__ __align__(16) bf16 g_W2T [H_SZ * H_SZ];
__device__ __align__(16) bf16 g_aWB [H_SZ * H_SZ];
__device__ __align__(16) bf16 g_WcT [H_SZ * H_SZ];
__device__ __align__(16) float g_wcp[WC_SPLIT * H_SZ * H_SZ];  // Wc partials
__device__ float g_r  [MQ * H_SZ];
__device__ float g_agg[MQ * H_SZ];
__device__ int   g_mask_is32;

// ---------------------------------------------------------------------------
// conv_all: segmented fp32->bf16 for 4 buffers + mask dtype detect (1 launch)
// ---------------------------------------------------------------------------
#define CN0 (M1 * D_SZ)
#define CN1 (MQ * H_SZ)
#define CN2 (H_SZ * H_SZ)
#define CN3 (H_SZ * H_SZ)
#define CNT (CN0 + CN1 + CN2 + CN3)
#define CONVB (CNT / 4 / 256)                 // 15296 full blocks
#define DETB ((NMASK / 2 + 255) / 256)        // 80 detect blocks

__global__ void conv_all_kernel(const float* __restrict__ p0,
                                const float* __restrict__ p1,
                                const float* __restrict__ p2,
                                const float* __restrict__ p3,
                                const long long* __restrict__ m64)
{
    if (blockIdx.x >= CONVB) {
        // mask dtype detection blocks
        int i = (blockIdx.x - CONVB) * 256 + threadIdx.x;
        if (i < NMASK / 2) {
            unsigned long long v = (unsigned long long)m64[i];
            if (v > 1ULL) atomicOr(&g_mask_is32, 1);
        }
        return;
    }
    long idx = ((long)blockIdx.x * 256 + threadIdx.x) * 4;
    const float* in;
    bf16* out;
    long off;
    if (idx < CN0)                    { in = p0; out = g_weB; off = idx; }
    else if (idx < CN0 + CN1)         { in = p1; out = g_loB; off = idx - CN0; }
    else if (idx < CN0 + CN1 + CN2)   { in = p2; out = g_W2B; off = idx - CN0 - CN1; }
    else                              { in = p3; out = g_aWB; off = idx - CN0 - CN1 - CN2; }
    float4 v = *reinterpret_cast<const float4*>(in + off);
    *reinterpret_cast<__nv_bfloat162*>(out + off)     = __floats2bfloat162_rn(v.x, v.y);
    *reinterpret_cast<__nv_bfloat162*>(out + off + 2) = __floats2bfloat162_rn(v.z, v.w);
}

// ---------------------------------------------------------------------------
// One transpose+convert launch for W1 and W2 (z selects)
// ---------------------------------------------------------------------------
__global__ void trans_all_kernel(const float* __restrict__ W1,
                                 const float* __restrict__ W2)
{
    const int z = blockIdx.z;
    const float* in = z ? W2 : W1;
    bf16* out = z ? g_W2T : g_W1T;
    const int K = z ? H_SZ : D_SZ;
    const int N = H_SZ;
    if (blockIdx.y * 32 >= K) return;

    __shared__ float tile[32][33];
    int x = blockIdx.x * 32 + threadIdx.x;
    int y0 = blockIdx.y * 32;
    #pragma unroll
    for (int j = 0; j < 32; j += 8) {
        int y = y0 + threadIdx.y + j;
        if (y < K && x < N)
            tile[threadIdx.y + j][threadIdx.x] = in[(size_t)y * N + x];
    }
    __syncthreads();
    int ox = y0 + threadIdx.x;
    int oy0 = blockIdx.x * 32;
    #pragma unroll
    for (int j = 0; j < 32; j += 8) {
        int oy = oy0 + threadIdx.y + j;
        if (oy < N && ox < K)
            out[(size_t)oy * K + ox] =
                __float2bfloat16_rn(tile[threadIdx.x][threadIdx.y + j]);
    }
}

// ---------------------------------------------------------------------------
// Shared GEMM machinery
// ---------------------------------------------------------------------------
#define BKQ 64
#define TSTRIDE 72
#define TILE_BF (128 * TSTRIDE)
#define SMEM_BYTES (4 * TILE_BF * 2)     // 73728 B -> 3 CTAs/SM (216KB)

__device__ __forceinline__ void cp_async16(uint32_t dst, const void* src, int ssize)
{
    asm volatile("cp.async.cg.shared.global [%0], [%1], 16, %2;\n"
                 :: "r"(dst), "l"(src), "r"(ssize));
}
__device__ __forceinline__ void cp_commit() { asm volatile("cp.async.commit_group;\n"); }
__device__ __forceinline__ void cp_wait0()  { asm volatile("cp.async.wait_group 0;\n"); }

#define MMA_BF16(acc, af, bf0, bf1)                                            \
    asm volatile(                                                              \
        "mma.sync.aligned.m16n8k16.row.col.f32.bf16.bf16.f32 "                 \
        "{%0,%1,%2,%3}, {%4,%5,%6,%7}, {%8,%9}, {%0,%1,%2,%3};\n"              \
        : "+f"((acc)[0]), "+f"((acc)[1]), "+f"((acc)[2]), "+f"((acc)[3])       \
        : "r"((af)[0]), "r"((af)[1]), "r"((af)[2]), "r"((af)[3]),              \
          "r"(bf0), "r"(bf1))

// Common mainloop body: computes acc over kt16 k16-steps with LDA-strided
// global rows. A, Bt are bf16 [rows][LDA].
#define GEMM_VARS()                                                            \
    const int tid  = threadIdx.x;                                              \
    const int lane = tid & 31;                                                 \
    const int wid  = tid >> 5;                                                 \
    const int wm   = (wid & 1) * 64;                                           \
    const int wn   = (wid >> 1) * 64;                                          \
    const int g    = lane >> 2;                                                \
    const int tg   = lane & 3;                                                 \
    const int crow = tid >> 3;                                                 \
    const int ac   = (tid & 7) * 8;

#define GEMM_BODY(A, Bt, LDA, K, m0, n0)                                       \
    uint32_t as_base[2], bs_base[2];                                           \
    as_base[0] = (uint32_t)__cvta_generic_to_shared(As[0]);                    \
    as_base[1] = (uint32_t)__cvta_generic_to_shared(As[1]);                    \
    bs_base[0] = (uint32_t)__cvta_generic_to_shared(Bs[0]);                    \
    bs_base[1] = (uint32_t)__cvta_generic_to_shared(Bs[1]);                    \
    float acc[4][8][4];                                                        \
    _Pragma("unroll")                                                          \
    for (int mi = 0; mi < 4; mi++)                                             \
        _Pragma("unroll")                                                      \
        for (int ni = 0; ni < 8; ni++)                                         \
            _Pragma("unroll")                                                  \
            for (int r = 0; r < 4; r++)                                        \
                acc[mi][ni][r] = 0.f;                                          \
    const int kt16  = ((K) + 15) >> 4;                                         \
    const int tiles = (kt16 + 3) >> 2;                                         \
    auto load_tile = [&](int buf, int k0) {                                    \
        int gk = k0 + ac;                                                      \
        int ok = (gk < (K)) ? 16 : 0;                                          \
        int gks = ok ? gk : 0;                                                 \
        _Pragma("unroll")                                                      \
        for (int i = 0; i < 8; i++) {                                          \
            int row = crow + 16 * i;                                           \
            cp_async16(as_base[buf] + (row * TSTRIDE + ac) * 2,                \
                       (A) + (size_t)((m0) + row) * (LDA) + gks, ok);          \
        }                                                                      \
        _Pragma("unroll")                                                      \
        for (int i = 0; i < 8; i++) {                                          \
            int row = crow + 16 * i;                                           \
            cp_async16(bs_base[buf] + (row * TSTRIDE + ac) * 2,                \
                       (Bt) + (size_t)((n0) + row) * (LDA) + gks, ok);         \
        }                                                                      \
        cp_commit();                                                           \
    };                                                                         \
    load_tile(0, 0);                                                           \
    int buf = 0;                                                               \
    for (int t = 0; t < tiles; t++) {                                          \
        cp_wait0();                                                            \
        __syncthreads();                                                       \
        if (t + 1 < tiles)                                                     \
            load_tile(buf ^ 1, (t + 1) * BKQ);                                 \
        const bf16* Ab = As[buf];                                              \
        const bf16* Bb = Bs[buf];                                              \
        const int slim = kt16 - (t << 2);                                      \
        _Pragma("unroll")                                                      \
        for (int s = 0; s < 4; s++) {                                          \
            if (s >= slim) break;                                              \
            const int kb = s * 16;                                             \
            uint32_t af[4][4];                                                 \
            _Pragma("unroll")                                                  \
            for (int mi = 0; mi < 4; mi++) {                                   \
                const bf16* p = Ab + (wm + mi * 16 + g) * TSTRIDE + kb + 2 * tg; \
                af[mi][0] = *reinterpret_cast<const uint32_t*>(p);             \
                af[mi][1] = *reinterpret_cast<const uint32_t*>(p + 8 * TSTRIDE); \
                af[mi][2] = *reinterpret_cast<const uint32_t*>(p + 8);         \
                af[mi][3] = *reinterpret_cast<const uint32_t*>(p + 8 * TSTRIDE + 8); \
            }                                                                  \
            uint32_t bfr[8][2];                                                \
            _Pragma("unroll")                                                  \
            for (int ni = 0; ni < 8; ni++) {                                   \
                const bf16* p = Bb + (wn + ni * 8 + g) * TSTRIDE + kb + 2 * tg; \
                bfr[ni][0] = *reinterpret_cast<const uint32_t*>(p);            \
                bfr[ni][1] = *reinterpret_cast<const uint32_t*>(p + 8);        \
            }                                                                  \
            _Pragma("unroll")                                                  \
            for (int mi = 0; mi < 4; mi++)                                     \
                _Pragma("unroll")                                              \
                for (int ni = 0; ni < 8; ni++)                                 \
                    MMA_BF16(acc[mi][ni], af[mi], bfr[ni][0], bfr[ni][1]);     \
        }                                                                      \
        buf ^= 1;                                                              \
    }

// ---------------------------------------------------------------------------
// Wc split-K GEMM: grid (6, 6, WC_SPLIT).
// partial[z][m][n] = sum_{h in chunk z} W2[m][h] * attn_W[n][h]  (fp32)
// ---------------------------------------------------------------------------
__global__ __launch_bounds__(128, 3)
void wc_gemm(void)
{
    extern __shared__ bf16 smem[];
    bf16* As[2] = { smem,                smem + TILE_BF };
    bf16* Bs[2] = { smem + 2 * TILE_BF,  smem + 3 * TILE_BF };
    GEMM_VARS();
    const int m0 = blockIdx.y * 128;
    const int n0 = blockIdx.x * 128;
    const int z  = blockIdx.z;
    const bf16* A  = g_W2B + z * 128;
    const bf16* Bt = g_aWB + z * 128;
    GEMM_BODY(A, Bt, H_SZ, 128, m0, n0);

    float* P = g_wcp + (size_t)z * H_SZ * H_SZ;
    #pragma unroll
    for (int ni = 0; ni < 8; ni++) {
        const int col = n0 + wn + ni * 8 + tg * 2;
        #pragma unroll
        for (int mi = 0; mi < 4; mi++) {
            const int row = m0 + wm + mi * 16 + g;
            *reinterpret_cast<float2*>(&P[(size_t)row * H_SZ + col]) =
                make_float2(acc[mi][ni][0], acc[mi][ni][1]);
            *reinterpret_cast<float2*>(&P[(size_t)(row + 8) * H_SZ + col]) =
                make_float2(acc[mi][ni][2], acc[mi][ni][3]);
        }
    }
}

// Reduce Wc partials (deterministic order) -> bf16 WcT
__global__ void wc_reduce(void)
{
    int i = (blockIdx.x * blockDim.x + threadIdx.x) * 4;
    if (i >= H_SZ * H_SZ) return;
    float4 s = *reinterpret_cast<const float4*>(g_wcp + i);
    #pragma unroll
    for (int z = 1; z < WC_SPLIT; z++) {
        float4 p = *reinterpret_cast<const float4*>(g_wcp + (size_t)z * H_SZ * H_SZ + i);
        s.x += p.x; s.y += p.y; s.z += p.z; s.w += p.w;
    }
    *reinterpret_cast<__nv_bfloat162*>(g_WcT + i)     = __floats2bfloat162_rn(s.x, s.y);
    *reinterpret_cast<__nv_bfloat162*>(g_WcT + i + 2) = __floats2bfloat162_rn(s.z, s.w);
}

// ---------------------------------------------------------------------------
// Merged GEMM1 + GEMM_r. grid (6, MB1 + MBQ).
// ---------------------------------------------------------------------------
__global__ __launch_bounds__(128, 3)
void gemm_main(const float* __restrict__ b1)
{
    extern __shared__ bf16 smem[];
    bf16* As[2] = { smem,                smem + TILE_BF };
    bf16* Bs[2] = { smem + 2 * TILE_BF,  smem + 3 * TILE_BF };
    GEMM_VARS();
    const int n0 = blockIdx.x * 128;
    const bool first = (blockIdx.y < MB1);
    const bf16* A  = first ? g_weB : g_loB;
    const bf16* Bt = first ? g_W1T : g_WcT;
    const int   K  = first ? D_SZ  : H_SZ;
    const int   m0 = (first ? blockIdx.y : (blockIdx.y - MB1)) * 128;
    GEMM_BODY(A, Bt, K, K, m0, n0);

    if (first) {
        #pragma unroll
        for (int ni = 0; ni < 8; ni++) {
            const int col = n0 + wn + ni * 8 + tg * 2;
            const float b0 = b1[col];
            const float bb1 = b1[col + 1];
            #pragma unroll
            for (int mi = 0; mi < 4; mi++) {
                const int row = m0 + wm + mi * 16 + g;
                float r0 = tanhf(acc[mi][ni][0] + b0);
                float r1 = tanhf(acc[mi][ni][1] + bb1);
                float r2 = tanhf(acc[mi][ni][2] + b0);
                float r3 = tanhf(acc[mi][ni][3] + bb1);
                *reinterpret_cast<__nv_bfloat162*>(&g_tmpB[(size_t)row * H_SZ + col]) =
                    __floats2bfloat162_rn(r0, r1);
                *reinterpret_cast<__nv_bfloat162*>(&g_tmpB[(size_t)(row + 8) * H_SZ + col]) =
                    __floats2bfloat162_rn(r2, r3);
            }
        }
    } else {
        #pragma unroll
        for (int ni = 0; ni < 8; ni++) {
            const int col = n0 + wn + ni * 8 + tg * 2;
            #pragma unroll
            for (int mi = 0; mi < 4; mi++) {
                const int row = m0 + wm + mi * 16 + g;
                *reinterpret_cast<float2*>(&g_r[(size_t)row * H_SZ + col]) =
                    make_float2(acc[mi][ni][0], acc[mi][ni][1]);
                *reinterpret_cast<float2*>(&g_r[(size_t)(row + 8) * H_SZ + col]) =
                    make_float2(acc[mi][ni][2], acc[mi][ni][3]);
            }
        }
    }
}

// ---------------------------------------------------------------------------
// GEMM_agg: agg = ctx @ W2 + b2 (fp32 out). grid (6, MBQ) — 1 wave @ 3/SM.
// ---------------------------------------------------------------------------
__global__ __launch_bounds__(128, 3)
void gemm_agg(const float* __restrict__ b2)
{
    extern __shared__ bf16 smem[];
    bf16* As[2] = { smem,                smem + TILE_BF };
    bf16* Bs[2] = { smem + 2 * TILE_BF,  smem + 3 * TILE_BF };
    GEMM_VARS();
    const int n0 = blockIdx.x * 128;
    const int m0 = blockIdx.y * 128;
    GEMM_BODY(g_ctxB, g_W2T, H_SZ, H_SZ, m0, n0);

    #pragma unroll
    for (int ni = 0; ni < 8; ni++) {
        const int col = n0 + wn + ni * 8 + tg * 2;
        const float b0 = b2[col];
        const float bb1 = b2[col + 1];
        #pragma unroll
        for (int mi = 0; mi < 4; mi++) {
            const int row = m0 + wm + mi * 16 + g;
            *reinterpret_cast<float2*>(&g_agg[(size_t)row * H_SZ + col]) =
                make_float2(acc[mi][ni][0] + b0, acc[mi][ni][1] + bb1);
            *reinterpret_cast<float2*>(&g_agg[(size_t)(row + 8) * H_SZ + col]) =
                make_float2(acc[mi][ni][2] + b0, acc[mi][ni][3] + bb1);
        }
    }
}

// ---------------------------------------------------------------------------
// Attention kernel (reads raw mask via dtype flag)
// ---------------------------------------------------------------------------
__global__ __launch_bounds__(256)
void attn_kernel(const void* __restrict__ mask, bf16* __restrict__ ctxB)
{
    const int bs  = blockIdx.x;
    const int tid = threadIdx.x;

    __shared__ float red[5][256];
    __shared__ float s_alpha[5];

    const float* rrow  = g_r    + (size_t)bs * H_SZ;
    const bf16*  trow  = g_tmpB + (size_t)bs * W_SZ * H_SZ;

    float rv[3], tv[5][3];
    #pragma unroll
    for (int e = 0; e < 3; e++) {
        int h = tid + e * 256;
        rv[e] = rrow[h];
        #pragma unroll
        for (int w = 0; w < W_SZ; w++)
            tv[w][e] = __bfloat162float(trow[w * H_SZ + h]);
    }

    #pragma unroll
    for (int w = 0; w < W_SZ; w++) {
        float d = 0.f;
        #pragma unroll
        for (int e = 0; e < 3; e++)
            d = fmaf(rv[e], tv[w][e], d);
        red[w][tid] = d;
    }
    __syncthreads();
    for (int s = 128; s > 0; s >>= 1) {
        if (tid < s) {
            #pragma unroll
            for (int w = 0; w < W_SZ; w++)
                red[w][tid] += red[w][tid + s];
        }
        __syncthreads();
    }

    if (tid == 0) {
        const bool is32 = (g_mask_is32 != 0);
        float sc[5];
        float mx = -1e30f;
        #pragma unroll
        for (int w = 0; w < W_SZ; w++) {
            float mk = is32
                ? (float)((const int*)mask)[(size_t)bs * W_SZ + w]
                : (float)((const long long*)mask)[(size_t)bs * W_SZ + w];
            sc[w] = red[w][0] + (1.f - mk) * (-10000.f);
            mx = fmaxf(mx, sc[w]);
        }
        float sum = 0.f;
        #pragma unroll
        for (int w = 0; w < W_SZ; w++) {
            sc[w] = expf(sc[w] - mx);
            sum += sc[w];
        }
        float inv = 1.f / sum;
        #pragma unroll
        for (int w = 0; w < W_SZ; w++)
            s_alpha[w] = sc[w] * inv;
    }
    __syncthreads();

    float alpha[5];
    #pragma unroll
    for (int w = 0; w < W_SZ; w++) alpha[w] = s_alpha[w];

    #pragma unroll
    for (int e = 0; e < 3; e++) {
        int h = tid + e * 256;
        float c = 0.f;
        #pragma unroll
        for (int w = 0; w < W_SZ; w++)
            c = fmaf(alpha[w], tv[w][e], c);
        ctxB[(size_t)bs * H_SZ + h] = __float2bfloat16_rn(c);
    }
}

// ---------------------------------------------------------------------------
// Residual + LayerNorm (proven)
// ---------------------------------------------------------------------------
__global__ __launch_bounds__(256)
void ln_kernel(const float* __restrict__ lo,
               const float* __restrict__ gamma,
               const float* __restrict__ beta,
               float* __restrict__ out)
{
    const int bs  = blockIdx.x;
    const int tid = threadIdx.x;

    __shared__ float red0[256], red1[256];

    const float* lorow = lo    + (size_t)bs * H_SZ;
    const float* agrow = g_agg + (size_t)bs * H_SZ;

    float hv[3];
    float psum = 0.f, psq = 0.f;
    #pragma unroll
    for (int e = 0; e < 3; e++) {
        int h = tid + e * 256;
        hv[e] = lorow[h] + agrow[h];
        psum += hv[e];
        psq  = fmaf(hv[e], hv[e], psq);
    }
    red0[tid] = psum;
    red1[tid] = psq;
    __syncthreads();
    for (int s = 128; s > 0; s >>= 1) {
        if (tid < s) {
            red0[tid] += red0[tid + s];
            red1[tid] += red1[tid + s];
        }
        __syncthreads();
    }

    const float inv_h = 1.f / (float)H_SZ;
    float mu   = red0[0] * inv_h;
    float var  = red1[0] * inv_h - mu * mu;
    float rstd = rsqrtf(var + 1e-12f);

    #pragma unroll
    for (int e = 0; e < 3; e++) {
        int h = tid + e * 256;
        out[(size_t)bs * H_SZ + h] = (hv[e] - mu) * rstd * gamma[h] + beta[h];
    }
}

// ---------------------------------------------------------------------------
// Launch
// ---------------------------------------------------------------------------
extern "C" void kernel_launch(void* const* d_in, const int* in_sizes, int n_in,
                              void* d_out, int out_size)
{
    const float* lo     = (const float*)d_in[0];
    const float* we_in  = (const float*)d_in[1];
    const void*  mask   = d_in[2];
    const float* W1     = (const float*)d_in[3];
    const float* b1     = (const float*)d_in[4];
    const float* W2     = (const float*)d_in[5];
    const float* b2     = (const float*)d_in[6];
    const float* attn_W = (const float*)d_in[7];
    const float* gamma  = (const float*)d_in[8];
    const float* beta   = (const float*)d_in[9];
    float*       out    = (float*)d_out;

    bf16 *ctxB_p;
    cudaGetSymbolAddress((void**)&ctxB_p, g_ctxB);

    cudaFuncSetAttribute(wc_gemm,   cudaFuncAttributeMaxDynamicSharedMemorySize, SMEM_BYTES);
    cudaFuncSetAttribute(gemm_main, cudaFuncAttributeMaxDynamicSharedMemorySize, SMEM_BYTES);
    cudaFuncSetAttribute(gemm_agg,  cudaFuncAttributeMaxDynamicSharedMemorySize, SMEM_BYTES);

    int* flag_p;
    cudaGetSymbolAddress((void**)&flag_p, g_mask_is32);
    cudaMemsetAsync(flag_p, 0, sizeof(int));

    // converts + mask detect in one launch
    conv_all_kernel<<<CONVB + DETB, 256>>>(we_in, lo, W2, attn_W,
                                           (const long long*)mask);
    // both weight transposes in one launch
    {
        dim3 tb(32, 8);
        dim3 tg(24, 24, 2);
        trans_all_kernel<<<tg, tb>>>(W1, W2);
    }

    dim3 blk(128);

    // Wc split-K: partials then ordered reduce
    wc_gemm<<<dim3(6, 6, WC_SPLIT), blk, SMEM_BYTES>>>();
    wc_reduce<<<(H_SZ * H_SZ / 4 + 255) / 256, 256>>>();
    // Merged GEMM1 (ragged K=200) + GEMM_r (K=768)
    gemm_main<<<dim3(6, MB1 + MBQ), blk, SMEM_BYTES>>>(b1);
    // Attention: scores, softmax, ctx (bf16)
    attn_kernel<<<MQ, 256>>>(mask, ctxB_p);
    // GEMM_agg: agg = ctx @ W2 + b2
    gemm_agg<<<dim3(6, MBQ), blk, SMEM_BYTES>>>(b2);
    // Residual + LayerNorm
    ln_kernel<<<MQ, 256>>>(lo, gamma, beta, out);
}

// round 12
// speedup vs baseline: 2.7776x; 1.0663x over previous
#include <cuda_runtime.h>
#include <cuda_bf16.h>
#include <math.h>
#include <stdint.h>

typedef __nv_bfloat16 bf16;

// Problem dimensions (fixed by the reference)
#define B_SZ 16
#define S_SZ 512
#define W_SZ 5
#define D_SZ 200
#define H_SZ 768
#define M1 (B_SZ * S_SZ * W_SZ)   // 40960
#define MQ (B_SZ * S_SZ)          // 8192
#define NMASK (MQ * W_SZ)         // 40960
#define MB1 (M1 / 128)            // 320
#define MBQ (MQ / 128)            // 64
#define WC_SPLIT 6

// Scratch (alloc-free rule: __device__ globals)
__device__ __align__(16) bf16 g_weB [M1 * D_SZ];
__device__ __align__(16) bf16 g_loB [MQ * H_SZ];
__device__ __align__(16) bf16 g_tmpB[M1 * H_SZ];
__device__ __align__(16) bf16 g_ctxB[MQ * H_SZ];
__device__ __align__(16) bf16 g_rB  [MQ * H_SZ];   // r = lo @ Wc (bf16)
__device__ __align__(16) bf16 g_W1T [H_SZ * D_SZ];
__device__ __align__(16) bf16 g_W2B [H_SZ * H_SZ];
__device__ __align__(16) bf16 g_W2T [H_SZ * H_SZ];
__device__ __align__(16) bf16 g_aWB [H_SZ * H_SZ];
__device__ __align__(16) bf16 g_WcT [H_SZ * H_SZ];
__device__ __align__(16) float g_wcp[WC_SPLIT * H_SZ * H_SZ];
__device__ float g_agg[MQ * H_SZ];
__device__ int   g_mask_is32;

// ---------------------------------------------------------------------------
// conv_all: segmented fp32->bf16 for 4 buffers + mask dtype detect (1 launch)
// ---------------------------------------------------------------------------
#define CN0 (M1 * D_SZ)
#define CN1 (MQ * H_SZ)
#define CN2 (H_SZ * H_SZ)
#define CN3 (H_SZ * H_SZ)
#define CNT (CN0 + CN1 + CN2 + CN3)
#define CONVB (CNT / 4 / 256)
#define DETB ((NMASK / 2 + 255) / 256)

__global__ void conv_all_kernel(const float* __restrict__ p0,
                                const float* __restrict__ p1,
                                const float* __restrict__ p2,
                                const float* __restrict__ p3,
                                const long long* __restrict__ m64)
{
    if (blockIdx.x >= CONVB) {
        int i = (blockIdx.x - CONVB) * 256 + threadIdx.x;
        if (i < NMASK / 2) {
            unsigned long long v = (unsigned long long)m64[i];
            if (v > 1ULL) atomicOr(&g_mask_is32, 1);
        }
        return;
    }
    long idx = ((long)blockIdx.x * 256 + threadIdx.x) * 4;
    const float* in;
    bf16* out;
    long off;
    if (idx < CN0)                    { in = p0; out = g_weB; off = idx; }
    else if (idx < CN0 + CN1)         { in = p1; out = g_loB; off = idx - CN0; }
    else if (idx < CN0 + CN1 + CN2)   { in = p2; out = g_W2B; off = idx - CN0 - CN1; }
    else                              { in = p3; out = g_aWB; off = idx - CN0 - CN1 - CN2; }
    float4 v = *reinterpret_cast<const float4*>(in + off);
    *reinterpret_cast<__nv_bfloat162*>(out + off)     = __floats2bfloat162_rn(v.x, v.y);
    *reinterpret_cast<__nv_bfloat162*>(out + off + 2) = __floats2bfloat162_rn(v.z, v.w);
}

// ---------------------------------------------------------------------------
// One transpose+convert launch for W1 and W2 (z selects)
// ---------------------------------------------------------------------------
__global__ void trans_all_kernel(const float* __restrict__ W1,
                                 const float* __restrict__ W2)
{
    const int z = blockIdx.z;
    const float* in = z ? W2 : W1;
    bf16* out = z ? g_W2T : g_W1T;
    const int K = z ? H_SZ : D_SZ;
    const int N = H_SZ;
    if (blockIdx.y * 32 >= K) return;

    __shared__ float tile[32][33];
    int x = blockIdx.x * 32 + threadIdx.x;
    int y0 = blockIdx.y * 32;
    #pragma unroll
    for (int j = 0; j < 32; j += 8) {
        int y = y0 + threadIdx.y + j;
        if (y < K && x < N)
            tile[threadIdx.y + j][threadIdx.x] = in[(size_t)y * N + x];
    }
    __syncthreads();
    int ox = y0 + threadIdx.x;
    int oy0 = blockIdx.x * 32;
    #pragma unroll
    for (int j = 0; j < 32; j += 8) {
        int oy = oy0 + threadIdx.y + j;
        if (oy < N && ox < K)
            out[(size_t)oy * K + ox] =
                __float2bfloat16_rn(tile[threadIdx.x][threadIdx.y + j]);
    }
}

// ---------------------------------------------------------------------------
// Shared GEMM machinery
// ---------------------------------------------------------------------------
#define BKQ 64
#define TSTRIDE 72
#define TILE_BF (128 * TSTRIDE)
#define SMEM_BYTES (4 * TILE_BF * 2)     // 73728 B -> 3 CTAs/SM

__device__ __forceinline__ void cp_async16(uint32_t dst, const void* src, int ssize)
{
    asm volatile("cp.async.cg.shared.global [%0], [%1], 16, %2;\n"
                 :: "r"(dst), "l"(src), "r"(ssize));
}
__device__ __forceinline__ void cp_commit() { asm volatile("cp.async.commit_group;\n"); }
__device__ __forceinline__ void cp_wait0()  { asm volatile("cp.async.wait_group 0;\n"); }

#define MMA_BF16(acc, af, bf0, bf1)                                            \
    asm volatile(                                                              \
        "mma.sync.aligned.m16n8k16.row.col.f32.bf16.bf16.f32 "                 \
        "{%0,%1,%2,%3}, {%4,%5,%6,%7}, {%8,%9}, {%0,%1,%2,%3};\n"              \
        : "+f"((acc)[0]), "+f"((acc)[1]), "+f"((acc)[2]), "+f"((acc)[3])       \
        : "r"((af)[0]), "r"((af)[1]), "r"((af)[2]), "r"((af)[3]),              \
          "r"(bf0), "r"(bf1))

#define GEMM_VARS()                                                            \
    const int tid  = threadIdx.x;                                              \
    const int lane = tid & 31;                                                 \
    const int wid  = tid >> 5;                                                 \
    const int wm   = (wid & 1) * 64;                                           \
    const int wn   = (wid >> 1) * 64;                                          \
    const int g    = lane >> 2;                                                \
    const int tg   = lane & 3;                                                 \
    const int crow = tid >> 3;                                                 \
    const int ac   = (tid & 7) * 8;

#define GEMM_BODY(A, Bt, LDA, K, m0, n0)                                       \
    uint32_t as_base[2], bs_base[2];                                           \
    as_base[0] = (uint32_t)__cvta_generic_to_shared(As[0]);                    \
    as_base[1] = (uint32_t)__cvta_generic_to_shared(As[1]);                    \
    bs_base[0] = (uint32_t)__cvta_generic_to_shared(Bs[0]);                    \
    bs_base[1] = (uint32_t)__cvta_generic_to_shared(Bs[1]);                    \
    float acc[4][8][4];                                                        \
    _Pragma("unroll")                                                          \
    for (int mi = 0; mi < 4; mi++)                                             \
        _Pragma("unroll")                                                      \
        for (int ni = 0; ni < 8; ni++)                                         \
            _Pragma("unroll")                                                  \
            for (int r = 0; r < 4; r++)                                        \
                acc[mi][ni][r] = 0.f;                                          \
    const int kt16  = ((K) + 15) >> 4;                                         \
    const int tiles = (kt16 + 3) >> 2;                                         \
    auto load_tile = [&](int buf, int k0) {                                    \
        int gk = k0 + ac;                                                      \
        int ok = (gk < (K)) ? 16 : 0;                                          \
        int gks = ok ? gk : 0;                                                 \
        _Pragma("unroll")                                                      \
        for (int i = 0; i < 8; i++) {                                          \
            int row = crow + 16 * i;                                           \
            cp_async16(as_base[buf] + (row * TSTRIDE + ac) * 2,                \
                       (A) + (size_t)((m0) + row) * (LDA) + gks, ok);          \
        }                                                                      \
        _Pragma("unroll")                                                      \
        for (int i = 0; i < 8; i++) {                                          \
            int row = crow + 16 * i;                                           \
            cp_async16(bs_base[buf] + (row * TSTRIDE + ac) * 2,                \
                       (Bt) + (size_t)((n0) + row) * (LDA) + gks, ok);         \
        }                                                                      \
        cp_commit();                                                           \
    };                                                                         \
    load_tile(0, 0);                                                           \
    int buf = 0;                                                               \
    for (int t = 0; t < tiles; t++) {                                          \
        cp_wait0();                                                            \
        __syncthreads();                                                       \
        if (t + 1 < tiles)                                                     \
            load_tile(buf ^ 1, (t + 1) * BKQ);                                 \
        const bf16* Ab = As[buf];                                              \
        const bf16* Bb = Bs[buf];                                              \
        const int slim = kt16 - (t << 2);                                      \
        _Pragma("unroll")                                                      \
        for (int s = 0; s < 4; s++) {                                          \
            if (s >= slim) break;                                              \
            const int kb = s * 16;                                             \
            uint32_t af[4][4];                                                 \
            _Pragma("unroll")                                                  \
            for (int mi = 0; mi < 4; mi++) {                                   \
                const bf16* p = Ab + (wm + mi * 16 + g) * TSTRIDE + kb + 2 * tg; \
                af[mi][0] = *reinterpret_cast<const uint32_t*>(p);             \
                af[mi][1] = *reinterpret_cast<const uint32_t*>(p + 8 * TSTRIDE); \
                af[mi][2] = *reinterpret_cast<const uint32_t*>(p + 8);         \
                af[mi][3] = *reinterpret_cast<const uint32_t*>(p + 8 * TSTRIDE + 8); \
            }                                                                  \
            uint32_t bfr[8][2];                                                \
            _Pragma("unroll")                                                  \
            for (int ni = 0; ni < 8; ni++) {                                   \
                const bf16* p = Bb + (wn + ni * 8 + g) * TSTRIDE + kb + 2 * tg; \
                bfr[ni][0] = *reinterpret_cast<const uint32_t*>(p);            \
                bfr[ni][1] = *reinterpret_cast<const uint32_t*>(p + 8);        \
            }                                                                  \
            _Pragma("unroll")                                                  \
            for (int mi = 0; mi < 4; mi++)                                     \
                _Pragma("unroll")                                              \
                for (int ni = 0; ni < 8; ni++)                                 \
                    MMA_BF16(acc[mi][ni], af[mi], bfr[ni][0], bfr[ni][1]);     \
        }                                                                      \
        buf ^= 1;                                                              \
    }

// ---------------------------------------------------------------------------
// Wc split-K GEMM: grid (6, 6, WC_SPLIT)
// ---------------------------------------------------------------------------
__global__ __launch_bounds__(128, 3)
void wc_gemm(void)
{
    extern __shared__ bf16 smem[];
    bf16* As[2] = { smem,                smem + TILE_BF };
    bf16* Bs[2] = { smem + 2 * TILE_BF,  smem + 3 * TILE_BF };
    GEMM_VARS();
    const int m0 = blockIdx.y * 128;
    const int n0 = blockIdx.x * 128;
    const int z  = blockIdx.z;
    const bf16* A  = g_W2B + z * 128;
    const bf16* Bt = g_aWB + z * 128;
    GEMM_BODY(A, Bt, H_SZ, 128, m0, n0);

    float* P = g_wcp + (size_t)z * H_SZ * H_SZ;
    #pragma unroll
    for (int ni = 0; ni < 8; ni++) {
        const int col = n0 + wn + ni * 8 + tg * 2;
        #pragma unroll
        for (int mi = 0; mi < 4; mi++) {
            const int row = m0 + wm + mi * 16 + g;
            *reinterpret_cast<float2*>(&P[(size_t)row * H_SZ + col]) =
                make_float2(acc[mi][ni][0], acc[mi][ni][1]);
            *reinterpret_cast<float2*>(&P[(size_t)(row + 8) * H_SZ + col]) =
                make_float2(acc[mi][ni][2], acc[mi][ni][3]);
        }
    }
}

__global__ void wc_reduce(void)
{
    int i = (blockIdx.x * blockDim.x + threadIdx.x) * 4;
    if (i >= H_SZ * H_SZ) return;
    float4 s = *reinterpret_cast<const float4*>(g_wcp + i);
    #pragma unroll
    for (int z = 1; z < WC_SPLIT; z++) {
        float4 p = *reinterpret_cast<const float4*>(g_wcp + (size_t)z * H_SZ * H_SZ + i);
        s.x += p.x; s.y += p.y; s.z += p.z; s.w += p.w;
    }
    *reinterpret_cast<__nv_bfloat162*>(g_WcT + i)     = __floats2bfloat162_rn(s.x, s.y);
    *reinterpret_cast<__nv_bfloat162*>(g_WcT + i + 2) = __floats2bfloat162_rn(s.z, s.w);
}

// ---------------------------------------------------------------------------
// GEMM1: tmpB = bf16(tanh(weB @ W1T^T + b1)), K=200. grid (6, MB1)
// ---------------------------------------------------------------------------
__global__ __launch_bounds__(128, 3)
void gemm1(const float* __restrict__ b1)
{
    extern __shared__ bf16 smem[];
    bf16* As[2] = { smem,                smem + TILE_BF };
    bf16* Bs[2] = { smem + 2 * TILE_BF,  smem + 3 * TILE_BF };
    GEMM_VARS();
    const int n0 = blockIdx.x * 128;
    const int m0 = blockIdx.y * 128;
    GEMM_BODY(g_weB, g_W1T, D_SZ, D_SZ, m0, n0);

    #pragma unroll
    for (int ni = 0; ni < 8; ni++) {
        const int col = n0 + wn + ni * 8 + tg * 2;
        const float b0 = b1[col];
        const float bb1 = b1[col + 1];
        #pragma unroll
        for (int mi = 0; mi < 4; mi++) {
            const int row = m0 + wm + mi * 16 + g;
            float r0 = tanhf(acc[mi][ni][0] + b0);
            float r1 = tanhf(acc[mi][ni][1] + bb1);
            float r2 = tanhf(acc[mi][ni][2] + b0);
            float r3 = tanhf(acc[mi][ni][3] + bb1);
            *reinterpret_cast<__nv_bfloat162*>(&g_tmpB[(size_t)row * H_SZ + col]) =
                __floats2bfloat162_rn(r0, r1);
            *reinterpret_cast<__nv_bfloat162*>(&g_tmpB[(size_t)(row + 8) * H_SZ + col]) =
                __floats2bfloat162_rn(r2, r3);
        }
    }
}

// ---------------------------------------------------------------------------
// GEMM_r: rB = bf16(loB @ WcT^T), K=768. grid (6, MBQ)
// ---------------------------------------------------------------------------
__global__ __launch_bounds__(128, 3)
void gemm_r(void)
{
    extern __shared__ bf16 smem[];
    bf16* As[2] = { smem,                smem + TILE_BF };
    bf16* Bs[2] = { smem + 2 * TILE_BF,  smem + 3 * TILE_BF };
    GEMM_VARS();
    const int n0 = blockIdx.x * 128;
    const int m0 = blockIdx.y * 128;
    GEMM_BODY(g_loB, g_WcT, H_SZ, H_SZ, m0, n0);

    #pragma unroll
    for (int ni = 0; ni < 8; ni++) {
        const int col = n0 + wn + ni * 8 + tg * 2;
        #pragma unroll
        for (int mi = 0; mi < 4; mi++) {
            const int row = m0 + wm + mi * 16 + g;
            *reinterpret_cast<__nv_bfloat162*>(&g_rB[(size_t)row * H_SZ + col]) =
                __floats2bfloat162_rn(acc[mi][ni][0], acc[mi][ni][1]);
            *reinterpret_cast<__nv_bfloat162*>(&g_rB[(size_t)(row + 8) * H_SZ + col]) =
                __floats2bfloat162_rn(acc[mi][ni][2], acc[mi][ni][3]);
        }
    }
}

// ---------------------------------------------------------------------------
// GEMM_agg: agg = ctx @ W2 + b2 (fp32 out). grid (6, MBQ)
// ---------------------------------------------------------------------------
__global__ __launch_bounds__(128, 3)
void gemm_agg(const float* __restrict__ b2)
{
    extern __shared__ bf16 smem[];
    bf16* As[2] = { smem,                smem + TILE_BF };
    bf16* Bs[2] = { smem + 2 * TILE_BF,  smem + 3 * TILE_BF };
    GEMM_VARS();
    const int n0 = blockIdx.x * 128;
    const int m0 = blockIdx.y * 128;
    GEMM_BODY(g_ctxB, g_W2T, H_SZ, H_SZ, m0, n0);

    #pragma unroll
    for (int ni = 0; ni < 8; ni++) {
        const int col = n0 + wn + ni * 8 + tg * 2;
        const float b0 = b2[col];
        const float bb1 = b2[col + 1];
        #pragma unroll
        for (int mi = 0; mi < 4; mi++) {
            const int row = m0 + wm + mi * 16 + g;
            *reinterpret_cast<float2*>(&g_agg[(size_t)row * H_SZ + col]) =
                make_float2(acc[mi][ni][0] + b0, acc[mi][ni][1] + bb1);
            *reinterpret_cast<float2*>(&g_agg[(size_t)(row + 8) * H_SZ + col]) =
                make_float2(acc[mi][ni][2] + b0, acc[mi][ni][3] + bb1);
        }
    }
}

// ---------------------------------------------------------------------------
// Attention kernel (r in bf16 now)
// ---------------------------------------------------------------------------
__global__ __launch_bounds__(256)
void attn_kernel(const void* __restrict__ mask, bf16* __restrict__ ctxB)
{
    const int bs  = blockIdx.x;
    const int tid = threadIdx.x;

    __shared__ float red[5][256];
    __shared__ float s_alpha[5];

    const bf16* rrow = g_rB   + (size_t)bs * H_SZ;
    const bf16* trow = g_tmpB + (size_t)bs * W_SZ * H_SZ;

    float rv[3], tv[5][3];
    #pragma unroll
    for (int e = 0; e < 3; e++) {
        int h = tid + e * 256;
        rv[e] = __bfloat162float(rrow[h]);
        #pragma unroll
        for (int w = 0; w < W_SZ; w++)
            tv[w][e] = __bfloat162float(trow[w * H_SZ + h]);
    }

    #pragma unroll
    for (int w = 0; w < W_SZ; w++) {
        float d = 0.f;
        #pragma unroll
        for (int e = 0; e < 3; e++)
            d = fmaf(rv[e], tv[w][e], d);
        red[w][tid] = d;
    }
    __syncthreads();
    for (int s = 128; s > 0; s >>= 1) {
        if (tid < s) {
            #pragma unroll
            for (int w = 0; w < W_SZ; w++)
                red[w][tid] += red[w][tid + s];
        }
        __syncthreads();
    }

    if (tid == 0) {
        const bool is32 = (g_mask_is32 != 0);
        float sc[5];
        float mx = -1e30f;
        #pragma unroll
        for (int w = 0; w < W_SZ; w++) {
            float mk = is32
                ? (float)((const int*)mask)[(size_t)bs * W_SZ + w]
                : (float)((const long long*)mask)[(size_t)bs * W_SZ + w];
            sc[w] = red[w][0] + (1.f - mk) * (-10000.f);
            mx = fmaxf(mx, sc[w]);
        }
        float sum = 0.f;
        #pragma unroll
        for (int w = 0; w < W_SZ; w++) {
            sc[w] = expf(sc[w] - mx);
            sum += sc[w];
        }
        float inv = 1.f / sum;
        #pragma unroll
        for (int w = 0; w < W_SZ; w++)
            s_alpha[w] = sc[w] * inv;
    }
    __syncthreads();

    float alpha[5];
    #pragma unroll
    for (int w = 0; w < W_SZ; w++) alpha[w] = s_alpha[w];

    #pragma unroll
    for (int e = 0; e < 3; e++) {
        int h = tid + e * 256;
        float c = 0.f;
        #pragma unroll
        for (int w = 0; w < W_SZ; w++)
            c = fmaf(alpha[w], tv[w][e], c);
        ctxB[(size_t)bs * H_SZ + h] = __float2bfloat16_rn(c);
    }
}

// ---------------------------------------------------------------------------
// Residual + LayerNorm (proven)
// ---------------------------------------------------------------------------
__global__ __launch_bounds__(256)
void ln_kernel(const float* __restrict__ lo,
               const float* __restrict__ gamma,
               const float* __restrict__ beta,
               float* __restrict__ out)
{
    const int bs  = blockIdx.x;
    const int tid = threadIdx.x;

    __shared__ float red0[256], red1[256];

    const float* lorow = lo    + (size_t)bs * H_SZ;
    const float* agrow = g_agg + (size_t)bs * H_SZ;

    float hv[3];
    float psum = 0.f, psq = 0.f;
    #pragma unroll
    for (int e = 0; e < 3; e++) {
        int h = tid + e * 256;
        hv[e] = lorow[h] + agrow[h];
        psum += hv[e];
        psq  = fmaf(hv[e], hv[e], psq);
    }
    red0[tid] = psum;
    red1[tid] = psq;
    __syncthreads();
    for (int s = 128; s > 0; s >>= 1) {
        if (tid < s) {
            red0[tid] += red0[tid + s];
            red1[tid] += red1[tid + s];
        }
        __syncthreads();
    }

    const float inv_h = 1.f / (float)H_SZ;
    float mu   = red0[0] * inv_h;
    float var  = red1[0] * inv_h - mu * mu;
    float rstd = rsqrtf(var + 1e-12f);

    #pragma unroll
    for (int e = 0; e < 3; e++) {
        int h = tid + e * 256;
        out[(size_t)bs * H_SZ + h] = (hv[e] - mu) * rstd * gamma[h] + beta[h];
    }
}

// ---------------------------------------------------------------------------
// Launch: forked graph.
//   main stream: memset, conv_all, trans_all, GEMM1 ............ join, attn, agg, ln
//   side stream:                         \-> wc_gemm, wc_reduce, gemm_r -/
// ---------------------------------------------------------------------------
extern "C" void kernel_launch(void* const* d_in, const int* in_sizes, int n_in,
                              void* d_out, int out_size)
{
    const float* lo     = (const float*)d_in[0];
    const float* we_in  = (const float*)d_in[1];
    const void*  mask   = d_in[2];
    const float* W1     = (const float*)d_in[3];
    const float* b1     = (const float*)d_in[4];
    const float* W2     = (const float*)d_in[5];
    const float* b2     = (const float*)d_in[6];
    const float* attn_W = (const float*)d_in[7];
    const float* gamma  = (const float*)d_in[8];
    const float* beta   = (const float*)d_in[9];
    float*       out    = (float*)d_out;

    bf16 *ctxB_p;
    cudaGetSymbolAddress((void**)&ctxB_p, g_ctxB);

    cudaFuncSetAttribute(wc_gemm,  cudaFuncAttributeMaxDynamicSharedMemorySize, SMEM_BYTES);
    cudaFuncSetAttribute(gemm1,    cudaFuncAttributeMaxDynamicSharedMemorySize, SMEM_BYTES);
    cudaFuncSetAttribute(gemm_r,   cudaFuncAttributeMaxDynamicSharedMemorySize, SMEM_BYTES);
    cudaFuncSetAttribute(gemm_agg, cudaFuncAttributeMaxDynamicSharedMemorySize, SMEM_BYTES);

    int* flag_p;
    cudaGetSymbolAddress((void**)&flag_p, g_mask_is32);

    cudaStream_t s1;
    cudaStreamCreateWithFlags(&s1, cudaStreamNonBlocking);
    cudaEvent_t evPrep, evR;
    cudaEventCreateWithFlags(&evPrep, cudaEventDisableTiming);
    cudaEventCreateWithFlags(&evR,    cudaEventDisableTiming);

    dim3 blk(128);

    // ---- main stream: preprocessing ----
    cudaMemsetAsync(flag_p, 0, sizeof(int));
    conv_all_kernel<<<CONVB + DETB, 256>>>(we_in, lo, W2, attn_W,
                                           (const long long*)mask);
    {
        dim3 tb(32, 8);
        dim3 tg(24, 24, 2);
        trans_all_kernel<<<tg, tb>>>(W1, W2);
    }
    cudaEventRecord(evPrep, 0);

    // ---- side stream: Wc chain + GEMM_r (independent of GEMM1) ----
    cudaStreamWaitEvent(s1, evPrep, 0);
    wc_gemm<<<dim3(6, 6, WC_SPLIT), blk, SMEM_BYTES, s1>>>();
    wc_reduce<<<(H_SZ * H_SZ / 4 + 255) / 256, 256, 0, s1>>>();
    gemm_r<<<dim3(6, MBQ), blk, SMEM_BYTES, s1>>>();
    cudaEventRecord(evR, s1);

    // ---- main stream: GEMM1 (concurrent with side stream) ----
    gemm1<<<dim3(6, MB1), blk, SMEM_BYTES>>>(b1);

    // ---- join, then the dependent tail ----
    cudaStreamWaitEvent(0, evR, 0);
    attn_kernel<<<MQ, 256>>>(mask, ctxB_p);
    gemm_agg<<<dim3(6, MBQ), blk, SMEM_BYTES>>>(b2);
    ln_kernel<<<MQ, 256>>>(lo, gamma, beta, out);

    cudaStreamDestroy(s1);
    cudaEventDestroy(evPrep);
    cudaEventDestroy(evR);
}